// round 2
// baseline (speedup 1.0000x reference)
#include <cuda_runtime.h>
#include <cstdint>

// ---------------------------------------------------------------------------
// Problem constants
// ---------------------------------------------------------------------------
#define Dm    512
#define Hh    8
#define DHh   64
#define DFFm  2048
#define Kk    4
#define Ss    4
#define Bb    4
#define LQ    4165          // 3136 + 784 + 196 + 49
#define NTOK  (Bb * LQ)     // 16660

// scale tables
__device__ __constant__ int c_wl[4]   = {56, 28, 14, 7};
__device__ __constant__ int c_hl[4]   = {56, 28, 14, 7};
__device__ __constant__ int c_offs[4] = {0, 3136, 3920, 4116};

// ---------------------------------------------------------------------------
// Scratch (static device arrays; no runtime allocation)
// ---------------------------------------------------------------------------
__device__ float g_Q  [(size_t)NTOK * Dm];
__device__ float g_REF[(size_t)NTOK * 2];
__device__ float g_V  [(size_t)NTOK * Dm];
__device__ float g_OFF[(size_t)NTOK * 256];
__device__ float g_ATT[(size_t)NTOK * 128];
__device__ float g_ACC[(size_t)NTOK * Dm];
__device__ float g_A2 [(size_t)NTOK * Dm];
__device__ float g_X  [(size_t)NTOK * Dm];
__device__ float g_H  [(size_t)NTOK * DFFm];
__device__ float g_Y  [(size_t)NTOK * Dm];

// ---------------------------------------------------------------------------
// Helpers
// ---------------------------------------------------------------------------
__device__ __forceinline__ int scale_of(int p, int& loc) {
    if (p < 3136)      { loc = p;        return 0; }
    else if (p < 3920) { loc = p - 3136; return 1; }
    else if (p < 4116) { loc = p - 3920; return 2; }
    else               { loc = p - 4116; return 3; }
}

// ---------------------------------------------------------------------------
// pack: srcs -> Q (concat layout), refs -> REF
// ---------------------------------------------------------------------------
__global__ void pack_q_kernel(const float* __restrict__ s0, const float* __restrict__ s1,
                              const float* __restrict__ s2, const float* __restrict__ s3,
                              float* __restrict__ Q)
{
    int e = blockIdx.x * blockDim.x + threadIdx.x;       // float4 units
    const int total = NTOK * (Dm / 4);
    if (e >= total) return;
    int n  = e >> 7;            // / 128
    int d4 = e & 127;
    int b = n / LQ;
    int p = n % LQ;
    int loc;
    int l = scale_of(p, loc);
    const float* src = (l == 0) ? s0 : (l == 1) ? s1 : (l == 2) ? s2 : s3;
    int lq = c_wl[l] * c_hl[l];
    float4 v = reinterpret_cast<const float4*>(src)[(size_t)(b * lq + loc) * 128 + d4];
    reinterpret_cast<float4*>(Q)[(size_t)n * 128 + d4] = v;
}

__global__ void pack_ref_kernel(const float* __restrict__ r0, const float* __restrict__ r1,
                                const float* __restrict__ r2, const float* __restrict__ r3,
                                float* __restrict__ REF)
{
    int n = blockIdx.x * blockDim.x + threadIdx.x;
    if (n >= NTOK) return;
    int b = n / LQ;
    int p = n % LQ;
    int loc;
    int l = scale_of(p, loc);
    const float* src = (l == 0) ? r0 : (l == 1) ? r1 : (l == 2) ? r2 : r3;
    int lq = c_wl[l] * c_hl[l];
    REF[(size_t)n * 2 + 0] = src[(size_t)(b * lq + loc) * 2 + 0];
    REF[(size_t)n * 2 + 1] = src[(size_t)(b * lq + loc) * 2 + 1];
}

// ---------------------------------------------------------------------------
// Tiled SGEMM: C[N,M] = A[N,Kd] @ W[Kd,M] + bias, optional ReLU.
// BM=64, BN=64, BK=16, TM=4, TN=4, 256 threads.
// ---------------------------------------------------------------------------
template<bool RELU>
__global__ void sgemm_bias_kernel(const float* __restrict__ A, const float* __restrict__ W,
                                  const float* __restrict__ bias, float* __restrict__ C,
                                  int N, int Kd, int M)
{
    const int BM = 64, BN = 64, BK = 16, TM = 4, TN = 4;
    __shared__ float As[BK][BM + 4];
    __shared__ float Bs[BK][BN];

    int tid = threadIdx.x;               // 0..255
    int tx  = tid % (BN / TN);           // 0..15
    int ty  = tid / (BN / TN);           // 0..15
    int rowBase = blockIdx.y * BM;
    int colBase = blockIdx.x * BN;

    // load mappings (float4 per thread)
    int aRow = tid / (BK / 4);           // 0..63
    int aCol = (tid % (BK / 4)) * 4;     // 0,4,8,12
    int bRow = tid / (BN / 4);           // 0..15
    int bCol = (tid % (BN / 4)) * 4;     // 0..60

    float acc[TM][TN];
#pragma unroll
    for (int i = 0; i < TM; i++)
#pragma unroll
        for (int j = 0; j < TN; j++) acc[i][j] = 0.f;

    for (int k0 = 0; k0 < Kd; k0 += BK) {
        float4 av = make_float4(0.f, 0.f, 0.f, 0.f);
        int gr = rowBase + aRow;
        if (gr < N)
            av = *reinterpret_cast<const float4*>(A + (size_t)gr * Kd + k0 + aCol);
        As[aCol + 0][aRow] = av.x;
        As[aCol + 1][aRow] = av.y;
        As[aCol + 2][aRow] = av.z;
        As[aCol + 3][aRow] = av.w;

        float4 wv = *reinterpret_cast<const float4*>(W + (size_t)(k0 + bRow) * M + colBase + bCol);
        *reinterpret_cast<float4*>(&Bs[bRow][bCol]) = wv;

        __syncthreads();
#pragma unroll
        for (int k = 0; k < BK; k++) {
            float4 ra = *reinterpret_cast<const float4*>(&As[k][ty * TM]);
            float4 rb = *reinterpret_cast<const float4*>(&Bs[k][tx * TN]);
            float am[4] = {ra.x, ra.y, ra.z, ra.w};
            float bm[4] = {rb.x, rb.y, rb.z, rb.w};
#pragma unroll
            for (int i = 0; i < TM; i++)
#pragma unroll
                for (int j = 0; j < TN; j++)
                    acc[i][j] = fmaf(am[i], bm[j], acc[i][j]);
        }
        __syncthreads();
    }

#pragma unroll
    for (int i = 0; i < TM; i++) {
        int r = rowBase + ty * TM + i;
        if (r >= N) continue;
#pragma unroll
        for (int j = 0; j < TN; j++) {
            int c = colBase + tx * TN + j;
            float v = acc[i][j] + bias[c];
            if (RELU) v = fmaxf(v, 0.f);
            C[(size_t)r * M + c] = v;
        }
    }
}

// ---------------------------------------------------------------------------
// softmax over groups of 16 (S*K) — one thread per (token, head)
// ---------------------------------------------------------------------------
__global__ void softmax16_kernel(float* __restrict__ ATT)
{
    int r = blockIdx.x * blockDim.x + threadIdx.x;
    if (r >= NTOK * Hh) return;
    float* p = ATT + (size_t)r * 16;
    float v[16], mx = -1e30f;
#pragma unroll
    for (int i = 0; i < 16; i++) { v[i] = p[i]; mx = fmaxf(mx, v[i]); }
    float s = 0.f;
#pragma unroll
    for (int i = 0; i < 16; i++) { v[i] = expf(v[i] - mx); s += v[i]; }
    float inv = 1.f / s;
#pragma unroll
    for (int i = 0; i < 16; i++) p[i] = v[i] * inv;
}

// ---------------------------------------------------------------------------
// Deformable bilinear sampling + attention aggregation.
// One warp per (token, head); lane handles dh = lane and lane+32.
// ---------------------------------------------------------------------------
__global__ void sample_kernel(const float* __restrict__ V, const float* __restrict__ OFF,
                              const float* __restrict__ ATT, const float* __restrict__ REF,
                              float* __restrict__ ACC)
{
    int wid = blockIdx.x * (blockDim.x / 32) + (threadIdx.x / 32);
    if (wid >= NTOK * Hh) return;
    int lane = threadIdx.x & 31;
    int n = wid / Hh;
    int h = wid % Hh;
    int b = n / LQ;

    float refx = REF[(size_t)n * 2 + 0];
    float refy = REF[(size_t)n * 2 + 1];

    float acc0 = 0.f, acc1 = 0.f;

#pragma unroll
    for (int s = 0; s < Ss; s++) {
        int wl = c_wl[s], hl = c_hl[s];
        int base_tok = b * LQ + c_offs[s];
        float fwl = (float)wl, fhl = (float)hl;
#pragma unroll
        for (int k = 0; k < Kk; k++) {
            float w  = ATT[(size_t)n * 128 + h * 16 + s * 4 + k];
            float ox = OFF[(size_t)n * 256 + (((h * 4 + s) * 4 + k) * 2) + 0];
            float oy = OFF[(size_t)n * 256 + (((h * 4 + s) * 4 + k) * 2) + 1];
            float x = refx * fwl + ox - 0.5f;
            float y = refy * fhl + oy - 0.5f;
            float x0f = floorf(x), y0f = floorf(y);
            int x0 = (int)x0f, y0 = (int)y0f;
            float wx1 = x - x0f, wx0 = 1.f - wx1;
            float wy1 = y - y0f, wy0 = 1.f - wy1;

#pragma unroll
            for (int c = 0; c < 4; c++) {
                int xi = x0 + (c & 1);
                int yi = y0 + (c >> 1);
                float wc = ((c & 1) ? wx1 : wx0) * ((c >> 1) ? wy1 : wy0);
                bool valid = (xi >= 0) && (xi < wl) && (yi >= 0) && (yi < hl);
                if (valid) {
                    int idx = yi * wl + xi;
                    const float* vp = V + ((size_t)(base_tok + idx) * Dm + h * DHh);
                    float ww = w * wc;
                    acc0 = fmaf(ww, __ldg(vp + lane),      acc0);
                    acc1 = fmaf(ww, __ldg(vp + lane + 32), acc1);
                }
            }
        }
    }
    ACC[(size_t)n * Dm + h * DHh + lane]      = acc0;
    ACC[(size_t)n * Dm + h * DHh + lane + 32] = acc1;
}

// ---------------------------------------------------------------------------
// Fused residual-add + LayerNorm.  out = LN(A + Bv) * g + be
// One block (128 threads) per token; each thread handles 4 elements.
// ---------------------------------------------------------------------------
__global__ void add_layernorm_kernel(const float* __restrict__ A, const float* __restrict__ Bv,
                                     const float* __restrict__ g, const float* __restrict__ be,
                                     float* __restrict__ out)
{
    int n = blockIdx.x;
    int t = threadIdx.x;   // 0..127
    float v[4];
    float s = 0.f, ss = 0.f;
#pragma unroll
    for (int i = 0; i < 4; i++) {
        int d = t + i * 128;
        float x = A[(size_t)n * Dm + d] + Bv[(size_t)n * Dm + d];
        v[i] = x; s += x; ss += x * x;
    }
#pragma unroll
    for (int o = 16; o > 0; o >>= 1) {
        s  += __shfl_xor_sync(0xffffffffu, s,  o);
        ss += __shfl_xor_sync(0xffffffffu, ss, o);
    }
    __shared__ float sh[8];
    int w = t >> 5, ln = t & 31;
    if (ln == 0) { sh[w] = s; sh[4 + w] = ss; }
    __syncthreads();
    float ts = sh[0] + sh[1] + sh[2] + sh[3];
    float tss = sh[4] + sh[5] + sh[6] + sh[7];
    float mu  = ts * (1.f / Dm);
    float var = tss * (1.f / Dm) - mu * mu;
    float inv = rsqrtf(var + 1e-5f);
#pragma unroll
    for (int i = 0; i < 4; i++) {
        int d = t + i * 128;
        out[(size_t)n * Dm + d] = (v[i] - mu) * inv * g[d] + be[d];
    }
}

// ---------------------------------------------------------------------------
// Launch
// ---------------------------------------------------------------------------
extern "C" void kernel_launch(void* const* d_in, const int* in_sizes, int n_in,
                              void* d_out, int out_size)
{
    // setup_inputs() builds the dict INTERLEAVED: src0, ref0, src1, ref1, ...
    // Bind the first 8 tensors by their (unique) element counts, so the
    // binding is independent of exact ordering.
    const float* srcs[4] = {nullptr, nullptr, nullptr, nullptr};
    const float* refs[4] = {nullptr, nullptr, nullptr, nullptr};
    const int src_sz[4] = {Bb * 56 * 56 * Dm, Bb * 28 * 28 * Dm, Bb * 14 * 14 * Dm, Bb * 7 * 7 * Dm};
    const int ref_sz[4] = {Bb * 56 * 56 * 2,  Bb * 28 * 28 * 2,  Bb * 14 * 14 * 2,  Bb * 7 * 7 * 2};
    for (int i = 0; i < 8; i++) {
        int sz = in_sizes[i];
        for (int l = 0; l < 4; l++) {
            if (sz == src_sz[l] && !srcs[l]) { srcs[l] = (const float*)d_in[i]; goto next; }
        }
        for (int l = 0; l < 4; l++) {
            if (sz == ref_sz[l] && !refs[l]) { refs[l] = (const float*)d_in[i]; goto next; }
        }
    next:;
    }

    const float* Wv    = (const float*)d_in[8];
    const float* bv    = (const float*)d_in[9];
    const float* Woff  = (const float*)d_in[10];
    const float* boff  = (const float*)d_in[11];
    const float* Wattn = (const float*)d_in[12];
    const float* battn = (const float*)d_in[13];
    const float* Wo    = (const float*)d_in[14];
    const float* bo    = (const float*)d_in[15];
    const float* W1    = (const float*)d_in[16];
    const float* b1    = (const float*)d_in[17];
    const float* W2    = (const float*)d_in[18];
    const float* b2    = (const float*)d_in[19];
    const float* g1    = (const float*)d_in[20];
    const float* be1   = (const float*)d_in[21];
    const float* g2    = (const float*)d_in[22];
    const float* be2   = (const float*)d_in[23];
    float* out = (float*)d_out;

    float *Q, *REF, *V, *OFF, *ATT, *ACC, *A2, *X, *Hb, *Y;
    cudaGetSymbolAddress((void**)&Q,   g_Q);
    cudaGetSymbolAddress((void**)&REF, g_REF);
    cudaGetSymbolAddress((void**)&V,   g_V);
    cudaGetSymbolAddress((void**)&OFF, g_OFF);
    cudaGetSymbolAddress((void**)&ATT, g_ATT);
    cudaGetSymbolAddress((void**)&ACC, g_ACC);
    cudaGetSymbolAddress((void**)&A2,  g_A2);
    cudaGetSymbolAddress((void**)&X,   g_X);
    cudaGetSymbolAddress((void**)&Hb,  g_H);
    cudaGetSymbolAddress((void**)&Y,   g_Y);

    // 1. pack
    {
        int total = NTOK * (Dm / 4);
        pack_q_kernel<<<(total + 255) / 256, 256>>>(srcs[0], srcs[1], srcs[2], srcs[3], Q);
        pack_ref_kernel<<<(NTOK + 255) / 256, 256>>>(refs[0], refs[1], refs[2], refs[3], REF);
    }

    dim3 blk(256);
    // 2. V = Q @ Wv + bv
    {
        dim3 grid(Dm / 64, (NTOK + 63) / 64);
        sgemm_bias_kernel<false><<<grid, blk>>>(Q, Wv, bv, V, NTOK, Dm, Dm);
    }
    // 3. OFF = Q @ Woff + boff
    {
        dim3 grid(256 / 64, (NTOK + 63) / 64);
        sgemm_bias_kernel<false><<<grid, blk>>>(Q, Woff, boff, OFF, NTOK, Dm, 256);
    }
    // 4. ATT = Q @ Wattn + battn
    {
        dim3 grid(128 / 64, (NTOK + 63) / 64);
        sgemm_bias_kernel<false><<<grid, blk>>>(Q, Wattn, battn, ATT, NTOK, Dm, 128);
    }
    // 5. softmax over 16
    softmax16_kernel<<<(NTOK * Hh + 255) / 256, 256>>>(ATT);
    // 6. deformable sampling
    {
        int warps = NTOK * Hh;
        sample_kernel<<<(warps + 7) / 8, 256>>>(V, OFF, ATT, REF, ACC);
    }
    // 7. A2 = ACC @ Wo + bo
    {
        dim3 grid(Dm / 64, (NTOK + 63) / 64);
        sgemm_bias_kernel<false><<<grid, blk>>>(ACC, Wo, bo, A2, NTOK, Dm, Dm);
    }
    // 8. X = LN(Q + A2)
    add_layernorm_kernel<<<NTOK, 128>>>(Q, A2, g1, be1, X);
    // 9. Hb = relu(X @ W1 + b1)
    {
        dim3 grid(DFFm / 64, (NTOK + 63) / 64);
        sgemm_bias_kernel<true><<<grid, blk>>>(X, W1, b1, Hb, NTOK, Dm, DFFm);
    }
    // 10. Y = Hb @ W2 + b2
    {
        dim3 grid(Dm / 64, (NTOK + 63) / 64);
        sgemm_bias_kernel<false><<<grid, blk>>>(Hb, W2, b2, Y, NTOK, DFFm, Dm);
    }
    // 11. out = LN(X + Y)
    add_layernorm_kernel<<<NTOK, 128>>>(X, Y, g2, be2, out);
}

// round 3
// speedup vs baseline: 1.0005x; 1.0005x over previous
#include <cuda_runtime.h>
#include <cstdint>

// ---------------------------------------------------------------------------
// Problem constants
// ---------------------------------------------------------------------------
#define Dm    512
#define Hh    8
#define DHh   64
#define DFFm  2048
#define Kk    4
#define Ss    4
#define Bb    4
#define LQ    4165          // 3136 + 784 + 196 + 49
#define NTOK  (Bb * LQ)     // 16660
#define MOA   384           // merged OFF(256) + ATT(128) output width

__device__ __constant__ int c_wl[4]   = {56, 28, 14, 7};
__device__ __constant__ int c_hl[4]   = {56, 28, 14, 7};
__device__ __constant__ int c_offs[4] = {0, 3136, 3920, 4116};

// ---------------------------------------------------------------------------
// Scratch
// ---------------------------------------------------------------------------
__device__ float g_Q  [(size_t)NTOK * Dm];
__device__ float g_REF[(size_t)NTOK * 2];
__device__ float g_V  [(size_t)NTOK * Dm];
__device__ float g_OA [(size_t)NTOK * MOA];   // cols 0..255 OFF, 256..383 ATT
__device__ float g_ACC[(size_t)NTOK * Dm];
__device__ float g_A2 [(size_t)NTOK * Dm];
__device__ float g_X  [(size_t)NTOK * Dm];
__device__ float g_H  [(size_t)NTOK * DFFm];
__device__ float g_Y  [(size_t)NTOK * Dm];
__device__ float g_Wc [(size_t)Dm * MOA];     // merged [Woff | Wattn]
__device__ float g_bc [MOA];

// ---------------------------------------------------------------------------
__device__ __forceinline__ int scale_of(int p, int& loc) {
    if (p < 3136)      { loc = p;        return 0; }
    else if (p < 3920) { loc = p - 3136; return 1; }
    else if (p < 4116) { loc = p - 3920; return 2; }
    else               { loc = p - 4116; return 3; }
}

// ---------------------------------------------------------------------------
// pack: srcs -> Q (concat layout), refs -> REF
// ---------------------------------------------------------------------------
__global__ void pack_q_kernel(const float* __restrict__ s0, const float* __restrict__ s1,
                              const float* __restrict__ s2, const float* __restrict__ s3,
                              float* __restrict__ Q)
{
    int e = blockIdx.x * blockDim.x + threadIdx.x;
    const int total = NTOK * (Dm / 4);
    if (e >= total) return;
    int n  = e >> 7;
    int d4 = e & 127;
    int b = n / LQ;
    int p = n % LQ;
    int loc;
    int l = scale_of(p, loc);
    const float* src = (l == 0) ? s0 : (l == 1) ? s1 : (l == 2) ? s2 : s3;
    int lq = c_wl[l] * c_hl[l];
    float4 v = reinterpret_cast<const float4*>(src)[(size_t)(b * lq + loc) * 128 + d4];
    reinterpret_cast<float4*>(Q)[(size_t)n * 128 + d4] = v;
}

__global__ void pack_ref_kernel(const float* __restrict__ r0, const float* __restrict__ r1,
                                const float* __restrict__ r2, const float* __restrict__ r3,
                                float* __restrict__ REF)
{
    int n = blockIdx.x * blockDim.x + threadIdx.x;
    if (n >= NTOK) return;
    int b = n / LQ;
    int p = n % LQ;
    int loc;
    int l = scale_of(p, loc);
    const float* src = (l == 0) ? r0 : (l == 1) ? r1 : (l == 2) ? r2 : r3;
    int lq = c_wl[l] * c_hl[l];
    REF[(size_t)n * 2 + 0] = src[(size_t)(b * lq + loc) * 2 + 0];
    REF[(size_t)n * 2 + 1] = src[(size_t)(b * lq + loc) * 2 + 1];
}

// merge Woff/Wattn into one [512,384] weight + bias
__global__ void merge_w_kernel(const float* __restrict__ Woff, const float* __restrict__ Wattn,
                               const float* __restrict__ boff, const float* __restrict__ battn,
                               float* __restrict__ Wc, float* __restrict__ bc)
{
    int i = blockIdx.x * blockDim.x + threadIdx.x;
    if (i < Dm * MOA) {
        int r = i / MOA, c = i % MOA;
        Wc[i] = (c < 256) ? Woff[r * 256 + c] : Wattn[r * 128 + (c - 256)];
    }
    if (i < MOA) bc[i] = (i < 256) ? boff[i] : battn[i - 256];
}

// ---------------------------------------------------------------------------
// SGEMM 128x128x8, TM=TN=8, 256 threads, double-buffered smem,
// register-prefetched global loads. C = A[N,Kd] @ W[Kd,M] + bias (+ReLU).
// Requires: M % 128 == 0, Kd % 8 == 0. N guarded.
// ---------------------------------------------------------------------------
template<bool RELU>
__global__ __launch_bounds__(256, 2)
void sgemm128_kernel(const float* __restrict__ A, const float* __restrict__ W,
                     const float* __restrict__ bias, float* __restrict__ C,
                     int N, int Kd, int M)
{
    __shared__ float As[2][8][132];
    __shared__ float Bs[2][8][128];

    const int tid = threadIdx.x;
    const int tx  = tid & 15;            // 0..15  (col groups of 8)
    const int ty  = tid >> 4;            // 0..15  (row groups of 8)
    const int rowBase = blockIdx.y * 128;
    const int colBase = blockIdx.x * 128;

    const int aRow = tid >> 1;           // 0..127
    const int aK   = (tid & 1) << 2;     // 0 or 4
    const int bK   = tid >> 5;           // 0..7
    const int bCol = (tid & 31) << 2;    // 0..124

    const int   gr    = rowBase + aRow;
    const bool  aOK   = (gr < N);
    const float* aPtr = A + (size_t)gr * Kd + aK;          // + k0
    const float* bPtr = W + (size_t)bK * M + colBase + bCol; // + k0*M

    float acc[8][8];
#pragma unroll
    for (int i = 0; i < 8; i++)
#pragma unroll
        for (int j = 0; j < 8; j++) acc[i][j] = 0.f;

    // preload tile 0
    float4 aReg = make_float4(0.f, 0.f, 0.f, 0.f);
    if (aOK) aReg = *reinterpret_cast<const float4*>(aPtr);
    float4 bReg = *reinterpret_cast<const float4*>(bPtr);

    As[0][aK + 0][aRow] = aReg.x;
    As[0][aK + 1][aRow] = aReg.y;
    As[0][aK + 2][aRow] = aReg.z;
    As[0][aK + 3][aRow] = aReg.w;
    *reinterpret_cast<float4*>(&Bs[0][bK][bCol]) = bReg;
    __syncthreads();

    const int nt = Kd >> 3;
    int buf = 0;
    for (int t = 0; t < nt; t++) {
        const bool pf = (t + 1 < nt);
        if (pf) {
            int k0n = (t + 1) << 3;
            aReg = make_float4(0.f, 0.f, 0.f, 0.f);
            if (aOK) aReg = *reinterpret_cast<const float4*>(aPtr + k0n);
            bReg = *reinterpret_cast<const float4*>(bPtr + (size_t)k0n * M);
        }

#pragma unroll
        for (int k = 0; k < 8; k++) {
            float4 a0 = *reinterpret_cast<const float4*>(&As[buf][k][ty * 8]);
            float4 a1 = *reinterpret_cast<const float4*>(&As[buf][k][ty * 8 + 4]);
            float4 b0 = *reinterpret_cast<const float4*>(&Bs[buf][k][tx * 8]);
            float4 b1 = *reinterpret_cast<const float4*>(&Bs[buf][k][tx * 8 + 4]);
            float am[8] = {a0.x, a0.y, a0.z, a0.w, a1.x, a1.y, a1.z, a1.w};
            float bm[8] = {b0.x, b0.y, b0.z, b0.w, b1.x, b1.y, b1.z, b1.w};
#pragma unroll
            for (int i = 0; i < 8; i++)
#pragma unroll
                for (int j = 0; j < 8; j++)
                    acc[i][j] = fmaf(am[i], bm[j], acc[i][j]);
        }

        if (pf) {
            int nb = buf ^ 1;
            As[nb][aK + 0][aRow] = aReg.x;
            As[nb][aK + 1][aRow] = aReg.y;
            As[nb][aK + 2][aRow] = aReg.z;
            As[nb][aK + 3][aRow] = aReg.w;
            *reinterpret_cast<float4*>(&Bs[nb][bK][bCol]) = bReg;
            __syncthreads();
            buf = nb;
        }
    }

    // epilogue
    float bvals[8];
#pragma unroll
    for (int j = 0; j < 8; j++) bvals[j] = bias[colBase + tx * 8 + j];

#pragma unroll
    for (int i = 0; i < 8; i++) {
        int r = rowBase + ty * 8 + i;
        if (r >= N) continue;
        float4 o0, o1;
        float v[8];
#pragma unroll
        for (int j = 0; j < 8; j++) {
            v[j] = acc[i][j] + bvals[j];
            if (RELU) v[j] = fmaxf(v[j], 0.f);
        }
        o0 = make_float4(v[0], v[1], v[2], v[3]);
        o1 = make_float4(v[4], v[5], v[6], v[7]);
        float* cp = C + (size_t)r * M + colBase + tx * 8;
        *reinterpret_cast<float4*>(cp)     = o0;
        *reinterpret_cast<float4*>(cp + 4) = o1;
    }
}

// ---------------------------------------------------------------------------
// softmax over groups of 16 (ATT lives in OA at col offset 256)
// ---------------------------------------------------------------------------
__global__ void softmax16_kernel(float* __restrict__ OA)
{
    int r = blockIdx.x * blockDim.x + threadIdx.x;    // (token, head)
    if (r >= NTOK * Hh) return;
    int n = r >> 3, h = r & 7;
    float* p = OA + (size_t)n * MOA + 256 + h * 16;
    float v[16], mx = -1e30f;
#pragma unroll
    for (int i = 0; i < 16; i++) { v[i] = p[i]; mx = fmaxf(mx, v[i]); }
    float s = 0.f;
#pragma unroll
    for (int i = 0; i < 16; i++) { v[i] = expf(v[i] - mx); s += v[i]; }
    float inv = 1.f / s;
#pragma unroll
    for (int i = 0; i < 16; i++) p[i] = v[i] * inv;
}

// ---------------------------------------------------------------------------
// Deformable bilinear sampling + aggregation. One warp per (token, head).
// ---------------------------------------------------------------------------
__global__ void sample_kernel(const float* __restrict__ V, const float* __restrict__ OA,
                              const float* __restrict__ REF, float* __restrict__ ACC)
{
    int wid = blockIdx.x * (blockDim.x / 32) + (threadIdx.x / 32);
    if (wid >= NTOK * Hh) return;
    int lane = threadIdx.x & 31;
    int n = wid / Hh;
    int h = wid % Hh;
    int b = n / LQ;

    float refx = REF[(size_t)n * 2 + 0];
    float refy = REF[(size_t)n * 2 + 1];

    const float* offp = OA + (size_t)n * MOA;          // OFF part
    const float* attp = OA + (size_t)n * MOA + 256;    // ATT part

    float acc0 = 0.f, acc1 = 0.f;

#pragma unroll
    for (int s = 0; s < Ss; s++) {
        int wl = c_wl[s], hl = c_hl[s];
        int base_tok = b * LQ + c_offs[s];
        float fwl = (float)wl, fhl = (float)hl;
#pragma unroll
        for (int k = 0; k < Kk; k++) {
            float w  = attp[h * 16 + s * 4 + k];
            float ox = offp[(((h * 4 + s) * 4 + k) * 2) + 0];
            float oy = offp[(((h * 4 + s) * 4 + k) * 2) + 1];
            float x = refx * fwl + ox - 0.5f;
            float y = refy * fhl + oy - 0.5f;
            float x0f = floorf(x), y0f = floorf(y);
            int x0 = (int)x0f, y0 = (int)y0f;
            float wx1 = x - x0f, wx0 = 1.f - wx1;
            float wy1 = y - y0f, wy0 = 1.f - wy1;

#pragma unroll
            for (int c = 0; c < 4; c++) {
                int xi = x0 + (c & 1);
                int yi = y0 + (c >> 1);
                float wc = ((c & 1) ? wx1 : wx0) * ((c >> 1) ? wy1 : wy0);
                bool valid = (xi >= 0) && (xi < wl) && (yi >= 0) && (yi < hl);
                if (valid) {
                    int idx = yi * wl + xi;
                    const float* vp = V + ((size_t)(base_tok + idx) * Dm + h * DHh);
                    float ww = w * wc;
                    acc0 = fmaf(ww, __ldg(vp + lane),      acc0);
                    acc1 = fmaf(ww, __ldg(vp + lane + 32), acc1);
                }
            }
        }
    }
    ACC[(size_t)n * Dm + h * DHh + lane]      = acc0;
    ACC[(size_t)n * Dm + h * DHh + lane + 32] = acc1;
}

// ---------------------------------------------------------------------------
// Fused residual-add + LayerNorm.
// ---------------------------------------------------------------------------
__global__ void add_layernorm_kernel(const float* __restrict__ A, const float* __restrict__ Bv,
                                     const float* __restrict__ g, const float* __restrict__ be,
                                     float* __restrict__ out)
{
    int n = blockIdx.x;
    int t = threadIdx.x;   // 0..127
    float v[4];
    float s = 0.f, ss = 0.f;
#pragma unroll
    for (int i = 0; i < 4; i++) {
        int d = t + i * 128;
        float x = A[(size_t)n * Dm + d] + Bv[(size_t)n * Dm + d];
        v[i] = x; s += x; ss += x * x;
    }
#pragma unroll
    for (int o = 16; o > 0; o >>= 1) {
        s  += __shfl_xor_sync(0xffffffffu, s,  o);
        ss += __shfl_xor_sync(0xffffffffu, ss, o);
    }
    __shared__ float sh[8];
    int w = t >> 5, ln = t & 31;
    if (ln == 0) { sh[w] = s; sh[4 + w] = ss; }
    __syncthreads();
    float ts  = sh[0] + sh[1] + sh[2] + sh[3];
    float tss = sh[4] + sh[5] + sh[6] + sh[7];
    float mu  = ts * (1.f / Dm);
    float var = tss * (1.f / Dm) - mu * mu;
    float inv = rsqrtf(var + 1e-5f);
#pragma unroll
    for (int i = 0; i < 4; i++) {
        int d = t + i * 128;
        out[(size_t)n * Dm + d] = (v[i] - mu) * inv * g[d] + be[d];
    }
}

// ---------------------------------------------------------------------------
// Launch
// ---------------------------------------------------------------------------
extern "C" void kernel_launch(void* const* d_in, const int* in_sizes, int n_in,
                              void* d_out, int out_size)
{
    // Inputs interleaved (src0, ref0, src1, ref1, ...). Bind by unique sizes.
    const float* srcs[4] = {nullptr, nullptr, nullptr, nullptr};
    const float* refs[4] = {nullptr, nullptr, nullptr, nullptr};
    const int src_sz[4] = {Bb * 56 * 56 * Dm, Bb * 28 * 28 * Dm, Bb * 14 * 14 * Dm, Bb * 7 * 7 * Dm};
    const int ref_sz[4] = {Bb * 56 * 56 * 2,  Bb * 28 * 28 * 2,  Bb * 14 * 14 * 2,  Bb * 7 * 7 * 2};
    for (int i = 0; i < 8; i++) {
        int sz = in_sizes[i];
        for (int l = 0; l < 4; l++) {
            if (sz == src_sz[l] && !srcs[l]) { srcs[l] = (const float*)d_in[i]; goto next; }
        }
        for (int l = 0; l < 4; l++) {
            if (sz == ref_sz[l] && !refs[l]) { refs[l] = (const float*)d_in[i]; goto next; }
        }
    next:;
    }

    const float* Wv    = (const float*)d_in[8];
    const float* bv    = (const float*)d_in[9];
    const float* Woff  = (const float*)d_in[10];
    const float* boff  = (const float*)d_in[11];
    const float* Wattn = (const float*)d_in[12];
    const float* battn = (const float*)d_in[13];
    const float* Wo    = (const float*)d_in[14];
    const float* bo    = (const float*)d_in[15];
    const float* W1    = (const float*)d_in[16];
    const float* b1    = (const float*)d_in[17];
    const float* W2    = (const float*)d_in[18];
    const float* b2    = (const float*)d_in[19];
    const float* g1    = (const float*)d_in[20];
    const float* be1   = (const float*)d_in[21];
    const float* g2    = (const float*)d_in[22];
    const float* be2   = (const float*)d_in[23];
    float* out = (float*)d_out;

    float *Q, *REF, *V, *OA, *ACC, *A2, *X, *Hb, *Y, *Wc, *bc;
    cudaGetSymbolAddress((void**)&Q,   g_Q);
    cudaGetSymbolAddress((void**)&REF, g_REF);
    cudaGetSymbolAddress((void**)&V,   g_V);
    cudaGetSymbolAddress((void**)&OA,  g_OA);
    cudaGetSymbolAddress((void**)&ACC, g_ACC);
    cudaGetSymbolAddress((void**)&A2,  g_A2);
    cudaGetSymbolAddress((void**)&X,   g_X);
    cudaGetSymbolAddress((void**)&Hb,  g_H);
    cudaGetSymbolAddress((void**)&Y,   g_Y);
    cudaGetSymbolAddress((void**)&Wc,  g_Wc);
    cudaGetSymbolAddress((void**)&bc,  g_bc);

    // 1. pack + weight merge
    {
        int total = NTOK * (Dm / 4);
        pack_q_kernel<<<(total + 255) / 256, 256>>>(srcs[0], srcs[1], srcs[2], srcs[3], Q);
        pack_ref_kernel<<<(NTOK + 255) / 256, 256>>>(refs[0], refs[1], refs[2], refs[3], REF);
        merge_w_kernel<<<(Dm * MOA + 255) / 256, 256>>>(Woff, Wattn, boff, battn, Wc, bc);
    }

    const int rowBlocks = (NTOK + 127) / 128;   // 131
    dim3 blk(256);

    // 2. V = Q @ Wv + bv
    sgemm128_kernel<false><<<dim3(Dm / 128, rowBlocks), blk>>>(Q, Wv, bv, V, NTOK, Dm, Dm);
    // 3. OA = Q @ [Woff|Wattn] + [boff|battn]
    sgemm128_kernel<false><<<dim3(MOA / 128, rowBlocks), blk>>>(Q, Wc, bc, OA, NTOK, Dm, MOA);
    // 4. softmax over 16
    softmax16_kernel<<<(NTOK * Hh + 255) / 256, 256>>>(OA);
    // 5. deformable sampling
    {
        int warps = NTOK * Hh;
        sample_kernel<<<(warps + 7) / 8, 256>>>(V, OA, REF, ACC);
    }
    // 6. A2 = ACC @ Wo + bo
    sgemm128_kernel<false><<<dim3(Dm / 128, rowBlocks), blk>>>(ACC, Wo, bo, A2, NTOK, Dm, Dm);
    // 7. X = LN(Q + A2)
    add_layernorm_kernel<<<NTOK, 128>>>(Q, A2, g1, be1, X);
    // 8. Hb = relu(X @ W1 + b1)
    sgemm128_kernel<true><<<dim3(DFFm / 128, rowBlocks), blk>>>(X, W1, b1, Hb, NTOK, Dm, DFFm);
    // 9. Y = Hb @ W2 + b2
    sgemm128_kernel<false><<<dim3(Dm / 128, rowBlocks), blk>>>(Hb, W2, b2, Y, NTOK, DFFm, Dm);
    // 10. out = LN(X + Y)
    add_layernorm_kernel<<<NTOK, 128>>>(X, Y, g2, be2, out);
}

// round 4
// speedup vs baseline: 1.8803x; 1.8794x over previous
#include <cuda_runtime.h>
#include <cuda_bf16.h>
#include <cstdint>

// ---------------------------------------------------------------------------
// Problem constants
// ---------------------------------------------------------------------------
#define Dm    512
#define Hh    8
#define DHh   64
#define DFFm  2048
#define Kk    4
#define Ss    4
#define Bb    4
#define LQ    4165
#define NTOK  (Bb * LQ)     // 16660
#define MOA   384

__device__ __constant__ int c_wl[4]   = {56, 28, 14, 7};
__device__ __constant__ int c_hl[4]   = {56, 28, 14, 7};
__device__ __constant__ int c_offs[4] = {0, 3136, 3920, 4116};

// ---------------------------------------------------------------------------
// Scratch
// ---------------------------------------------------------------------------
__device__ float g_Q  [(size_t)NTOK * Dm];
__device__ float g_REF[(size_t)NTOK * 2];
__device__ float g_V  [(size_t)NTOK * Dm];
__device__ float g_OA [(size_t)NTOK * MOA];
__device__ float g_A2 [(size_t)NTOK * Dm];
__device__ float g_X  [(size_t)NTOK * Dm];
__device__ float g_Y  [(size_t)NTOK * Dm];
__device__ float g_Wc [(size_t)Dm * MOA];
__device__ float g_bc [MOA];

// bf16 hi/lo buffers: activations [N, 2K], weights [2K, M]
__device__ __nv_bfloat16 g_Qhl  [(size_t)NTOK * 2 * Dm];
__device__ __nv_bfloat16 g_ACChl[(size_t)NTOK * 2 * Dm];
__device__ __nv_bfloat16 g_Xhl  [(size_t)NTOK * 2 * Dm];
__device__ __nv_bfloat16 g_Hbhl [(size_t)NTOK * 2 * DFFm];
__device__ __nv_bfloat16 g_Wvhl [(size_t)2 * Dm * Dm];
__device__ __nv_bfloat16 g_Wchl [(size_t)2 * Dm * MOA];
__device__ __nv_bfloat16 g_Wohl [(size_t)2 * Dm * Dm];
__device__ __nv_bfloat16 g_W1hl [(size_t)2 * Dm * DFFm];
__device__ __nv_bfloat16 g_W2hl [(size_t)2 * DFFm * Dm];

// ---------------------------------------------------------------------------
__device__ __forceinline__ int scale_of(int p, int& loc) {
    if (p < 3136)      { loc = p;        return 0; }
    else if (p < 3920) { loc = p - 3136; return 1; }
    else if (p < 4116) { loc = p - 3920; return 2; }
    else               { loc = p - 4116; return 3; }
}

__device__ __forceinline__ void split2(float v, __nv_bfloat16& hi, __nv_bfloat16& lo) {
    hi = __float2bfloat16(v);
    lo = __float2bfloat16(v - __bfloat162float(hi));
}

// ---------------------------------------------------------------------------
// pack: srcs -> Q (f32) + Qhl (bf16 hi/lo), refs -> REF
// ---------------------------------------------------------------------------
__global__ void pack_q_kernel(const float* __restrict__ s0, const float* __restrict__ s1,
                              const float* __restrict__ s2, const float* __restrict__ s3,
                              float* __restrict__ Q, __nv_bfloat16* __restrict__ Qhl)
{
    int e = blockIdx.x * blockDim.x + threadIdx.x;
    const int total = NTOK * (Dm / 4);
    if (e >= total) return;
    int n  = e >> 7;
    int d4 = e & 127;
    int b = n / LQ;
    int p = n % LQ;
    int loc;
    int l = scale_of(p, loc);
    const float* src = (l == 0) ? s0 : (l == 1) ? s1 : (l == 2) ? s2 : s3;
    int lq = c_wl[l] * c_hl[l];
    float4 v = reinterpret_cast<const float4*>(src)[(size_t)(b * lq + loc) * 128 + d4];
    reinterpret_cast<float4*>(Q)[(size_t)n * 128 + d4] = v;

    float vs[4] = {v.x, v.y, v.z, v.w};
    __nv_bfloat16 hi[4], lo[4];
#pragma unroll
    for (int i = 0; i < 4; i++) split2(vs[i], hi[i], lo[i]);
    size_t base = (size_t)n * (2 * Dm) + d4 * 4;
    *reinterpret_cast<uint2*>(Qhl + base)      = *reinterpret_cast<uint2*>(hi);
    *reinterpret_cast<uint2*>(Qhl + base + Dm) = *reinterpret_cast<uint2*>(lo);
}

__global__ void pack_ref_kernel(const float* __restrict__ r0, const float* __restrict__ r1,
                                const float* __restrict__ r2, const float* __restrict__ r3,
                                float* __restrict__ REF)
{
    int n = blockIdx.x * blockDim.x + threadIdx.x;
    if (n >= NTOK) return;
    int b = n / LQ;
    int p = n % LQ;
    int loc;
    int l = scale_of(p, loc);
    const float* src = (l == 0) ? r0 : (l == 1) ? r1 : (l == 2) ? r2 : r3;
    int lq = c_wl[l] * c_hl[l];
    REF[(size_t)n * 2 + 0] = src[(size_t)(b * lq + loc) * 2 + 0];
    REF[(size_t)n * 2 + 1] = src[(size_t)(b * lq + loc) * 2 + 1];
}

__global__ void merge_w_kernel(const float* __restrict__ Woff, const float* __restrict__ Wattn,
                               const float* __restrict__ boff, const float* __restrict__ battn,
                               float* __restrict__ Wc, float* __restrict__ bc)
{
    int i = blockIdx.x * blockDim.x + threadIdx.x;
    if (i < Dm * MOA) {
        int r = i / MOA, c = i % MOA;
        Wc[i] = (c < 256) ? Woff[r * 256 + c] : Wattn[r * 128 + (c - 256)];
    }
    if (i < MOA) bc[i] = (i < 256) ? boff[i] : battn[i - 256];
}

// split fp32 weight [K,M] -> bf16 [2K,M]: rows 0..K-1 hi, K..2K-1 lo
__global__ void split_w_kernel(const float* __restrict__ W, __nv_bfloat16* __restrict__ out,
                               int K, int M)
{
    int i = blockIdx.x * blockDim.x + threadIdx.x;
    if (i >= K * M) return;
    int k = i / M, m = i % M;
    __nv_bfloat16 hi, lo;
    split2(W[i], hi, lo);
    out[(size_t)k * M + m]       = hi;
    out[(size_t)(K + k) * M + m] = lo;
}

// ---------------------------------------------------------------------------
// bf16x3 GEMM via mma.sync.m16n8k16.
//   C[N,M] = Ahl[N,2K] (*) Whl[2K,M] + bias     (logical K' = 3K)
// k' < K   : Ahi x Whi ;  K<=k'<2K : Ahi x Wlo ;  2K<=k' : Alo x Whi
// Tiles: BM=128, BN=128, BK=32 (k'), 8 warps each 64x32, double-buffered smem.
// MODE 0: fp32 out (+bias). MODE 1: relu then bf16 hi/lo out [N, 2M].
// ---------------------------------------------------------------------------
#define LDSM4(r, addr) \
    asm volatile("ldmatrix.sync.aligned.m8n8.x4.shared.b16 {%0,%1,%2,%3}, [%4];" \
                 : "=r"((r)[0]), "=r"((r)[1]), "=r"((r)[2]), "=r"((r)[3]) : "r"(addr))
#define LDSM2T(r, addr) \
    asm volatile("ldmatrix.sync.aligned.m8n8.x2.trans.shared.b16 {%0,%1}, [%2];" \
                 : "=r"((r)[0]), "=r"((r)[1]) : "r"(addr))
#define MMA16816(c, a, b) \
    asm volatile("mma.sync.aligned.m16n8k16.row.col.f32.bf16.bf16.f32 " \
                 "{%0,%1,%2,%3}, {%4,%5,%6,%7}, {%8,%9}, {%0,%1,%2,%3};" \
                 : "+f"((c)[0]), "+f"((c)[1]), "+f"((c)[2]), "+f"((c)[3]) \
                 : "r"((a)[0]), "r"((a)[1]), "r"((a)[2]), "r"((a)[3]), \
                   "r"((b)[0]), "r"((b)[1]))

template<int MODE>
__global__ __launch_bounds__(256, 2)
void gemm_bf16x3_kernel(const __nv_bfloat16* __restrict__ Ahl,
                        const __nv_bfloat16* __restrict__ Whl,
                        const float* __restrict__ bias, void* __restrict__ Cout,
                        int N, int K, int M)
{
    __shared__ __nv_bfloat16 As[2][128][40];   // 80B row stride
    __shared__ __nv_bfloat16 Bs[2][32][136];   // 272B row stride

    const int tid  = threadIdx.x;
    const int lane = tid & 31;
    const int wid  = tid >> 5;
    const int wm = (wid & 1) * 64;
    const int wn = (wid >> 1) * 32;
    const int rowBase = blockIdx.y * 128;
    const int colBase = blockIdx.x * 128;

    // global load mapping
    const int aRow  = tid >> 1;               // 0..127
    const int aCol16 = (tid & 1) * 16;
    const int bRow  = tid >> 3;               // 0..31
    const int bCol16 = (tid & 7) * 16;
    const int gRowA = rowBase + aRow;
    const bool aOK  = (gRowA < N);
    const __nv_bfloat16* aRowPtr = Ahl + (size_t)gRowA * (2 * K);
    const __nv_bfloat16* bColPtr = Whl + colBase + bCol16;

    const int ntiles = (3 * K) >> 5;

    // ldmatrix smem addresses (u32 shared space)
    uint32_t asBase = (uint32_t)__cvta_generic_to_shared(&As[0][0][0]);
    uint32_t bsBase = (uint32_t)__cvta_generic_to_shared(&Bs[0][0][0]);
    const int lrow  = lane & 15;
    const int lcolA = (lane >> 4) * 8;
    // A frag addr = asBase + buf*10240 + (wm + mt*16 + lrow)*80 + (ks*16 + lcolA)*2
    uint32_t aFragBase = asBase + (wm + lrow) * 80 + lcolA * 2;
    // B frag addr = bsBase + buf*8704 + (ks*16 + lrow)*272 + (wn + nt*8)*2
    uint32_t bFragBase = bsBase + lrow * 272 + wn * 2;
    // smem store addresses
    uint32_t aStAddr = asBase + aRow * 80 + aCol16 * 2;
    uint32_t bStAddr = bsBase + bRow * 272 + bCol16 * 2;

    float acc[4][4][4];
#pragma unroll
    for (int i = 0; i < 4; i++)
#pragma unroll
        for (int j = 0; j < 4; j++)
#pragma unroll
            for (int r = 0; r < 4; r++) acc[i][j][r] = 0.f;

    auto ldGlobal = [&](int t, uint4& a0, uint4& a1, uint4& b0, uint4& b1) {
        int kp0 = t << 5;
        int aSeg = (kp0 < K) ? kp0 : kp0 - K;
        int wSeg = (kp0 < 2 * K) ? kp0 : kp0 - 2 * K;
        if (aOK) {
            const uint4* pa = reinterpret_cast<const uint4*>(aRowPtr + aSeg + aCol16);
            a0 = pa[0]; a1 = pa[1];
        } else {
            a0 = make_uint4(0, 0, 0, 0); a1 = a0;
        }
        const uint4* pb = reinterpret_cast<const uint4*>(bColPtr + (size_t)(wSeg + bRow) * M);
        b0 = pb[0]; b1 = pb[1];
    };
    auto stShared = [&](int buf, const uint4& a0, const uint4& a1,
                        const uint4& b0, const uint4& b1) {
        uint32_t ad = aStAddr + buf * 10240;
        uint32_t bd = bStAddr + buf * 8704;
        asm volatile("st.shared.v4.b32 [%0], {%1,%2,%3,%4};" :: "r"(ad),
                     "r"(a0.x), "r"(a0.y), "r"(a0.z), "r"(a0.w));
        asm volatile("st.shared.v4.b32 [%0], {%1,%2,%3,%4};" :: "r"(ad + 16),
                     "r"(a1.x), "r"(a1.y), "r"(a1.z), "r"(a1.w));
        asm volatile("st.shared.v4.b32 [%0], {%1,%2,%3,%4};" :: "r"(bd),
                     "r"(b0.x), "r"(b0.y), "r"(b0.z), "r"(b0.w));
        asm volatile("st.shared.v4.b32 [%0], {%1,%2,%3,%4};" :: "r"(bd + 16),
                     "r"(b1.x), "r"(b1.y), "r"(b1.z), "r"(b1.w));
    };

    {
        uint4 a0, a1, b0, b1;
        ldGlobal(0, a0, a1, b0, b1);
        stShared(0, a0, a1, b0, b1);
    }
    __syncthreads();

    int buf = 0;
    for (int t = 0; t < ntiles; t++) {
        uint4 a0, a1, b0, b1;
        const bool pf = (t + 1 < ntiles);
        if (pf) ldGlobal(t + 1, a0, a1, b0, b1);

#pragma unroll
        for (int ks = 0; ks < 2; ks++) {
            uint32_t af[4][4];
            uint32_t bfr[4][2];
            uint32_t aB = aFragBase + buf * 10240 + ks * 32;
            uint32_t bB = bFragBase + buf * 8704 + ks * 4352;
#pragma unroll
            for (int mt = 0; mt < 4; mt++) LDSM4(af[mt], aB + mt * 1280);
#pragma unroll
            for (int nt = 0; nt < 4; nt++) LDSM2T(bfr[nt], bB + nt * 16);
#pragma unroll
            for (int mt = 0; mt < 4; mt++)
#pragma unroll
                for (int nt = 0; nt < 4; nt++)
                    MMA16816(acc[mt][nt], af[mt], bfr[nt]);
        }

        if (pf) {
            stShared(buf ^ 1, a0, a1, b0, b1);
            __syncthreads();
            buf ^= 1;
        }
    }

    // epilogue
    float* Cf = (float*)Cout;
    __nv_bfloat16* Cb = (__nv_bfloat16*)Cout;
    const int mr = lane >> 2;          // 0..7
    const int nc = (lane & 3) * 2;     // 0,2,4,6

#pragma unroll
    for (int mt = 0; mt < 4; mt++) {
#pragma unroll
        for (int nt = 0; nt < 4; nt++) {
            int n0 = colBase + wn + nt * 8 + nc;
            float bb0 = bias[n0], bb1 = bias[n0 + 1];
#pragma unroll
            for (int half = 0; half < 2; half++) {
                int m = rowBase + wm + mt * 16 + mr + half * 8;
                if (m >= N) continue;
                float v0 = acc[mt][nt][half * 2 + 0] + bb0;
                float v1 = acc[mt][nt][half * 2 + 1] + bb1;
                if (MODE == 0) {
                    *reinterpret_cast<float2*>(Cf + (size_t)m * M + n0) = make_float2(v0, v1);
                } else {
                    v0 = fmaxf(v0, 0.f); v1 = fmaxf(v1, 0.f);
                    __nv_bfloat16 h0, l0, h1, l1;
                    split2(v0, h0, l0); split2(v1, h1, l1);
                    __nv_bfloat16* rp = Cb + (size_t)m * (2 * M);
                    __nv_bfloat162 hv; hv.x = h0; hv.y = h1;
                    __nv_bfloat162 lv; lv.x = l0; lv.y = l1;
                    *reinterpret_cast<__nv_bfloat162*>(rp + n0)     = hv;
                    *reinterpret_cast<__nv_bfloat162*>(rp + M + n0) = lv;
                }
            }
        }
    }
}

// ---------------------------------------------------------------------------
// softmax over groups of 16 (ATT lives in OA at col offset 256)
// ---------------------------------------------------------------------------
__global__ void softmax16_kernel(float* __restrict__ OA)
{
    int r = blockIdx.x * blockDim.x + threadIdx.x;
    if (r >= NTOK * Hh) return;
    int n = r >> 3, h = r & 7;
    float* p = OA + (size_t)n * MOA + 256 + h * 16;
    float v[16], mx = -1e30f;
#pragma unroll
    for (int i = 0; i < 16; i++) { v[i] = p[i]; mx = fmaxf(mx, v[i]); }
    float s = 0.f;
#pragma unroll
    for (int i = 0; i < 16; i++) { v[i] = expf(v[i] - mx); s += v[i]; }
    float inv = 1.f / s;
#pragma unroll
    for (int i = 0; i < 16; i++) p[i] = v[i] * inv;
}

// ---------------------------------------------------------------------------
// Deformable sampling; writes ACC directly as bf16 hi/lo [N, 2*Dm]
// ---------------------------------------------------------------------------
__global__ void sample_kernel(const float* __restrict__ V, const float* __restrict__ OA,
                              const float* __restrict__ REF, __nv_bfloat16* __restrict__ ACChl)
{
    int wid = blockIdx.x * (blockDim.x / 32) + (threadIdx.x / 32);
    if (wid >= NTOK * Hh) return;
    int lane = threadIdx.x & 31;
    int n = wid / Hh;
    int h = wid % Hh;
    int b = n / LQ;

    float refx = REF[(size_t)n * 2 + 0];
    float refy = REF[(size_t)n * 2 + 1];
    const float* offp = OA + (size_t)n * MOA;
    const float* attp = OA + (size_t)n * MOA + 256;

    float acc0 = 0.f, acc1 = 0.f;

#pragma unroll
    for (int s = 0; s < Ss; s++) {
        int wl = c_wl[s], hl = c_hl[s];
        int base_tok = b * LQ + c_offs[s];
        float fwl = (float)wl, fhl = (float)hl;
#pragma unroll
        for (int k = 0; k < Kk; k++) {
            float w  = attp[h * 16 + s * 4 + k];
            float ox = offp[(((h * 4 + s) * 4 + k) * 2) + 0];
            float oy = offp[(((h * 4 + s) * 4 + k) * 2) + 1];
            float x = refx * fwl + ox - 0.5f;
            float y = refy * fhl + oy - 0.5f;
            float x0f = floorf(x), y0f = floorf(y);
            int x0 = (int)x0f, y0 = (int)y0f;
            float wx1 = x - x0f, wx0 = 1.f - wx1;
            float wy1 = y - y0f, wy0 = 1.f - wy1;
#pragma unroll
            for (int c = 0; c < 4; c++) {
                int xi = x0 + (c & 1);
                int yi = y0 + (c >> 1);
                float wc = ((c & 1) ? wx1 : wx0) * ((c >> 1) ? wy1 : wy0);
                bool valid = (xi >= 0) && (xi < wl) && (yi >= 0) && (yi < hl);
                if (valid) {
                    int idx = yi * wl + xi;
                    const float* vp = V + ((size_t)(base_tok + idx) * Dm + h * DHh);
                    float ww = w * wc;
                    acc0 = fmaf(ww, __ldg(vp + lane),      acc0);
                    acc1 = fmaf(ww, __ldg(vp + lane + 32), acc1);
                }
            }
        }
    }
    __nv_bfloat16 h0, l0, h1, l1;
    split2(acc0, h0, l0);
    split2(acc1, h1, l1);
    size_t base = (size_t)n * (2 * Dm) + h * DHh;
    ACChl[base + lane]           = h0;
    ACChl[base + lane + 32]      = h1;
    ACChl[base + Dm + lane]      = l0;
    ACChl[base + Dm + lane + 32] = l1;
}

// ---------------------------------------------------------------------------
// Fused residual-add + LayerNorm; optionally also emits bf16 hi/lo copy.
// ---------------------------------------------------------------------------
__global__ void add_layernorm_kernel(const float* __restrict__ A, const float* __restrict__ Bv,
                                     const float* __restrict__ g, const float* __restrict__ be,
                                     float* __restrict__ out, __nv_bfloat16* __restrict__ outhl)
{
    int n = blockIdx.x;
    int t = threadIdx.x;   // 0..127
    float v[4];
    float s = 0.f, ss = 0.f;
#pragma unroll
    for (int i = 0; i < 4; i++) {
        int d = t + i * 128;
        float x = A[(size_t)n * Dm + d] + Bv[(size_t)n * Dm + d];
        v[i] = x; s += x; ss += x * x;
    }
#pragma unroll
    for (int o = 16; o > 0; o >>= 1) {
        s  += __shfl_xor_sync(0xffffffffu, s,  o);
        ss += __shfl_xor_sync(0xffffffffu, ss, o);
    }
    __shared__ float sh[8];
    int w = t >> 5, ln = t & 31;
    if (ln == 0) { sh[w] = s; sh[4 + w] = ss; }
    __syncthreads();
    float ts  = sh[0] + sh[1] + sh[2] + sh[3];
    float tss = sh[4] + sh[5] + sh[6] + sh[7];
    float mu  = ts * (1.f / Dm);
    float var = tss * (1.f / Dm) - mu * mu;
    float inv = rsqrtf(var + 1e-5f);
#pragma unroll
    for (int i = 0; i < 4; i++) {
        int d = t + i * 128;
        float o = (v[i] - mu) * inv * g[d] + be[d];
        out[(size_t)n * Dm + d] = o;
        if (outhl) {
            __nv_bfloat16 hi, lo;
            split2(o, hi, lo);
            outhl[(size_t)n * (2 * Dm) + d]      = hi;
            outhl[(size_t)n * (2 * Dm) + Dm + d] = lo;
        }
    }
}

// ---------------------------------------------------------------------------
// Launch
// ---------------------------------------------------------------------------
extern "C" void kernel_launch(void* const* d_in, const int* in_sizes, int n_in,
                              void* d_out, int out_size)
{
    const float* srcs[4] = {nullptr, nullptr, nullptr, nullptr};
    const float* refs[4] = {nullptr, nullptr, nullptr, nullptr};
    const int src_sz[4] = {Bb * 56 * 56 * Dm, Bb * 28 * 28 * Dm, Bb * 14 * 14 * Dm, Bb * 7 * 7 * Dm};
    const int ref_sz[4] = {Bb * 56 * 56 * 2,  Bb * 28 * 28 * 2,  Bb * 14 * 14 * 2,  Bb * 7 * 7 * 2};
    for (int i = 0; i < 8; i++) {
        int sz = in_sizes[i];
        for (int l = 0; l < 4; l++) {
            if (sz == src_sz[l] && !srcs[l]) { srcs[l] = (const float*)d_in[i]; goto next; }
        }
        for (int l = 0; l < 4; l++) {
            if (sz == ref_sz[l] && !refs[l]) { refs[l] = (const float*)d_in[i]; goto next; }
        }
    next:;
    }

    const float* Wv    = (const float*)d_in[8];
    const float* bv    = (const float*)d_in[9];
    const float* Woff  = (const float*)d_in[10];
    const float* boff  = (const float*)d_in[11];
    const float* Wattn = (const float*)d_in[12];
    const float* battn = (const float*)d_in[13];
    const float* Wo    = (const float*)d_in[14];
    const float* bo    = (const float*)d_in[15];
    const float* W1    = (const float*)d_in[16];
    const float* b1    = (const float*)d_in[17];
    const float* W2    = (const float*)d_in[18];
    const float* b2    = (const float*)d_in[19];
    const float* g1    = (const float*)d_in[20];
    const float* be1   = (const float*)d_in[21];
    const float* g2    = (const float*)d_in[22];
    const float* be2   = (const float*)d_in[23];
    float* out = (float*)d_out;

    float *Q, *REF, *V, *OA, *A2, *X, *Y, *Wc, *bc;
    __nv_bfloat16 *Qhl, *ACChl, *Xhl, *Hbhl, *Wvhl, *Wchl, *Wohl, *W1hl, *W2hl;
    cudaGetSymbolAddress((void**)&Q,    g_Q);
    cudaGetSymbolAddress((void**)&REF,  g_REF);
    cudaGetSymbolAddress((void**)&V,    g_V);
    cudaGetSymbolAddress((void**)&OA,   g_OA);
    cudaGetSymbolAddress((void**)&A2,   g_A2);
    cudaGetSymbolAddress((void**)&X,    g_X);
    cudaGetSymbolAddress((void**)&Y,    g_Y);
    cudaGetSymbolAddress((void**)&Wc,   g_Wc);
    cudaGetSymbolAddress((void**)&bc,   g_bc);
    cudaGetSymbolAddress((void**)&Qhl,  g_Qhl);
    cudaGetSymbolAddress((void**)&ACChl,g_ACChl);
    cudaGetSymbolAddress((void**)&Xhl,  g_Xhl);
    cudaGetSymbolAddress((void**)&Hbhl, g_Hbhl);
    cudaGetSymbolAddress((void**)&Wvhl, g_Wvhl);
    cudaGetSymbolAddress((void**)&Wchl, g_Wchl);
    cudaGetSymbolAddress((void**)&Wohl, g_Wohl);
    cudaGetSymbolAddress((void**)&W1hl, g_W1hl);
    cudaGetSymbolAddress((void**)&W2hl, g_W2hl);

    // 1. pack + weight prep
    {
        int total = NTOK * (Dm / 4);
        pack_q_kernel<<<(total + 255) / 256, 256>>>(srcs[0], srcs[1], srcs[2], srcs[3], Q, Qhl);
        pack_ref_kernel<<<(NTOK + 255) / 256, 256>>>(refs[0], refs[1], refs[2], refs[3], REF);
        merge_w_kernel<<<(Dm * MOA + 255) / 256, 256>>>(Woff, Wattn, boff, battn, Wc, bc);
        split_w_kernel<<<(Dm * Dm + 255) / 256, 256>>>(Wv, Wvhl, Dm, Dm);
        split_w_kernel<<<(Dm * MOA + 255) / 256, 256>>>(Wc, Wchl, Dm, MOA);
        split_w_kernel<<<(Dm * Dm + 255) / 256, 256>>>(Wo, Wohl, Dm, Dm);
        split_w_kernel<<<(Dm * DFFm + 255) / 256, 256>>>(W1, W1hl, Dm, DFFm);
        split_w_kernel<<<(DFFm * Dm + 255) / 256, 256>>>(W2, W2hl, DFFm, Dm);
    }

    const int rowBlocks = (NTOK + 127) / 128;   // 131
    dim3 blk(256);

    // 2. V = Q @ Wv + bv
    gemm_bf16x3_kernel<0><<<dim3(Dm / 128, rowBlocks), blk>>>(Qhl, Wvhl, bv, V, NTOK, Dm, Dm);
    // 3. OA = Q @ [Woff|Wattn] + bias
    gemm_bf16x3_kernel<0><<<dim3(MOA / 128, rowBlocks), blk>>>(Qhl, Wchl, bc, OA, NTOK, Dm, MOA);
    // 4. softmax
    softmax16_kernel<<<(NTOK * Hh + 255) / 256, 256>>>(OA);
    // 5. sampling -> ACChl
    {
        int warps = NTOK * Hh;
        sample_kernel<<<(warps + 7) / 8, 256>>>(V, OA, REF, ACChl);
    }
    // 6. A2 = ACC @ Wo + bo
    gemm_bf16x3_kernel<0><<<dim3(Dm / 128, rowBlocks), blk>>>(ACChl, Wohl, bo, A2, NTOK, Dm, Dm);
    // 7. X = LN(Q + A2)  (+ Xhl)
    add_layernorm_kernel<<<NTOK, 128>>>(Q, A2, g1, be1, X, Xhl);
    // 8. Hbhl = split(relu(X @ W1 + b1))
    gemm_bf16x3_kernel<1><<<dim3(DFFm / 128, rowBlocks), blk>>>(Xhl, W1hl, b1, Hbhl, NTOK, Dm, DFFm);
    // 9. Y = Hb @ W2 + b2
    gemm_bf16x3_kernel<0><<<dim3(Dm / 128, rowBlocks), blk>>>(Hbhl, W2hl, b2, Y, NTOK, DFFm, Dm);
    // 10. out = LN(X + Y)
    add_layernorm_kernel<<<NTOK, 128>>>(X, Y, g2, be2, out, nullptr);
}

// round 6
// speedup vs baseline: 1.9517x; 1.0380x over previous
#include <cuda_runtime.h>
#include <cuda_bf16.h>
#include <cstdint>

// ---------------------------------------------------------------------------
// Problem constants
// ---------------------------------------------------------------------------
#define Dm    512
#define Hh    8
#define DHh   64
#define DFFm  2048
#define Kk    4
#define Ss    4
#define Bb    4
#define LQ    4165
#define NTOK  (Bb * LQ)     // 16660
#define MVOA  896           // merged V(512) + OFF(256) + ATT(128)

__device__ __constant__ int c_wl[4]   = {56, 28, 14, 7};
__device__ __constant__ int c_hl[4]   = {56, 28, 14, 7};
__device__ __constant__ int c_offs[4] = {0, 3136, 3920, 4116};

// ---------------------------------------------------------------------------
// Scratch
// ---------------------------------------------------------------------------
__device__ float g_Q   [(size_t)NTOK * Dm];
__device__ float g_REF [(size_t)NTOK * 2];
__device__ float g_VOA [(size_t)NTOK * MVOA];   // V | OFF | ATT
__device__ float g_A2  [(size_t)NTOK * Dm];
__device__ float g_X   [(size_t)NTOK * Dm];
__device__ float g_Y   [(size_t)NTOK * Dm];
__device__ float g_Wall[(size_t)Dm * MVOA];
__device__ float g_ball[MVOA];

// bf16 hi/lo buffers: activations [N, 2K], weights [2K, M]
__device__ __nv_bfloat16 g_Qhl  [(size_t)NTOK * 2 * Dm];
__device__ __nv_bfloat16 g_ACChl[(size_t)NTOK * 2 * Dm];
__device__ __nv_bfloat16 g_Xhl  [(size_t)NTOK * 2 * Dm];
__device__ __nv_bfloat16 g_Hbhl [(size_t)NTOK * 2 * DFFm];
__device__ __nv_bfloat16 g_Wahl [(size_t)2 * Dm * MVOA];
__device__ __nv_bfloat16 g_Wohl [(size_t)2 * Dm * Dm];
__device__ __nv_bfloat16 g_W1hl [(size_t)2 * Dm * DFFm];
__device__ __nv_bfloat16 g_W2hl [(size_t)2 * DFFm * Dm];

// ---------------------------------------------------------------------------
__device__ __forceinline__ int scale_of(int p, int& loc) {
    if (p < 3136)      { loc = p;        return 0; }
    else if (p < 3920) { loc = p - 3136; return 1; }
    else if (p < 4116) { loc = p - 3920; return 2; }
    else               { loc = p - 4116; return 3; }
}
__device__ __forceinline__ void split2(float v, __nv_bfloat16& hi, __nv_bfloat16& lo) {
    hi = __float2bfloat16(v);
    lo = __float2bfloat16(v - __bfloat162float(hi));
}

// ---------------------------------------------------------------------------
// pack: srcs -> Q fp32 + Qhl; refs -> REF
// ---------------------------------------------------------------------------
__global__ void pack_q_kernel(const float* __restrict__ s0, const float* __restrict__ s1,
                              const float* __restrict__ s2, const float* __restrict__ s3,
                              float* __restrict__ Q, __nv_bfloat16* __restrict__ Qhl)
{
    int e = blockIdx.x * blockDim.x + threadIdx.x;
    const int total = NTOK * (Dm / 4);
    if (e >= total) return;
    int n  = e >> 7;
    int d4 = e & 127;
    int b = n / LQ;
    int p = n % LQ;
    int loc;
    int l = scale_of(p, loc);
    const float* src = (l == 0) ? s0 : (l == 1) ? s1 : (l == 2) ? s2 : s3;
    int lq = c_wl[l] * c_hl[l];
    float4 v = reinterpret_cast<const float4*>(src)[(size_t)(b * lq + loc) * 128 + d4];
    reinterpret_cast<float4*>(Q)[(size_t)n * 128 + d4] = v;

    float vs[4] = {v.x, v.y, v.z, v.w};
    __nv_bfloat16 hi[4], lo[4];
#pragma unroll
    for (int i = 0; i < 4; i++) split2(vs[i], hi[i], lo[i]);
    size_t base = (size_t)n * (2 * Dm) + d4 * 4;
    *reinterpret_cast<uint2*>(Qhl + base)      = *reinterpret_cast<uint2*>(hi);
    *reinterpret_cast<uint2*>(Qhl + base + Dm) = *reinterpret_cast<uint2*>(lo);
}

__global__ void pack_ref_kernel(const float* __restrict__ r0, const float* __restrict__ r1,
                                const float* __restrict__ r2, const float* __restrict__ r3,
                                float* __restrict__ REF)
{
    int n = blockIdx.x * blockDim.x + threadIdx.x;
    if (n >= NTOK) return;
    int b = n / LQ;
    int p = n % LQ;
    int loc;
    int l = scale_of(p, loc);
    const float* src = (l == 0) ? r0 : (l == 1) ? r1 : (l == 2) ? r2 : r3;
    int lq = c_wl[l] * c_hl[l];
    REF[(size_t)n * 2 + 0] = src[(size_t)(b * lq + loc) * 2 + 0];
    REF[(size_t)n * 2 + 1] = src[(size_t)(b * lq + loc) * 2 + 1];
}

// merge Wv/Woff/Wattn into one [512,896] weight + bias
__global__ void merge_w_kernel(const float* __restrict__ Wv, const float* __restrict__ Woff,
                               const float* __restrict__ Wattn,
                               const float* __restrict__ bv, const float* __restrict__ boff,
                               const float* __restrict__ battn,
                               float* __restrict__ Wall, float* __restrict__ ball)
{
    int i = blockIdx.x * blockDim.x + threadIdx.x;
    if (i < Dm * MVOA) {
        int r = i / MVOA, c = i % MVOA;
        float w;
        if (c < 512)       w = Wv[r * 512 + c];
        else if (c < 768)  w = Woff[r * 256 + (c - 512)];
        else               w = Wattn[r * 128 + (c - 768)];
        Wall[i] = w;
    }
    if (i < MVOA)
        ball[i] = (i < 512) ? bv[i] : (i < 768) ? boff[i - 512] : battn[i - 768];
}

// split fp32 weight [K,M] -> bf16 [2K,M]
__global__ void split_w_kernel(const float* __restrict__ W, __nv_bfloat16* __restrict__ out,
                               int K, int M)
{
    int i = blockIdx.x * blockDim.x + threadIdx.x;
    if (i >= K * M) return;
    int k = i / M, m = i % M;
    __nv_bfloat16 hi, lo;
    split2(W[i], hi, lo);
    out[(size_t)k * M + m]       = hi;
    out[(size_t)(K + k) * M + m] = lo;
}

// ---------------------------------------------------------------------------
// bf16x3 GEMM via mma.sync.m16n8k16 with 3-stage cp.async pipeline.
//   C[N,M] = Ahl[N,2K] (*) Whl[2K,M] + bias     (logical K' = 3K)
// 128x128x32 tiles, 8 warps (64x32 each), stages of (A 10240B + B 8704B).
// MODE 0: fp32 out (+bias). MODE 1: relu then bf16 hi/lo out [N, 2M].
// ---------------------------------------------------------------------------
#define LDSM4(r, addr) \
    asm volatile("ldmatrix.sync.aligned.m8n8.x4.shared.b16 {%0,%1,%2,%3}, [%4];" \
                 : "=r"((r)[0]), "=r"((r)[1]), "=r"((r)[2]), "=r"((r)[3]) : "r"(addr))
#define LDSM2T(r, addr) \
    asm volatile("ldmatrix.sync.aligned.m8n8.x2.trans.shared.b16 {%0,%1}, [%2];" \
                 : "=r"((r)[0]), "=r"((r)[1]) : "r"(addr))
#define MMA16816(c, a, b) \
    asm volatile("mma.sync.aligned.m16n8k16.row.col.f32.bf16.bf16.f32 " \
                 "{%0,%1,%2,%3}, {%4,%5,%6,%7}, {%8,%9}, {%0,%1,%2,%3};" \
                 : "+f"((c)[0]), "+f"((c)[1]), "+f"((c)[2]), "+f"((c)[3]) \
                 : "r"((a)[0]), "r"((a)[1]), "r"((a)[2]), "r"((a)[3]), \
                   "r"((b)[0]), "r"((b)[1]))

#define STAGE_BYTES 18944            // 10240 (A) + 8704 (B)
#define SMEM_GEMM   (3 * STAGE_BYTES)

template<int MODE>
__global__ __launch_bounds__(256, 2)
void gemm_bf16x3_kernel(const __nv_bfloat16* __restrict__ Ahl,
                        const __nv_bfloat16* __restrict__ Whl,
                        const float* __restrict__ bias, void* __restrict__ Cout,
                        int N, int K, int M)
{
    extern __shared__ char smem[];
    const uint32_t sdata = (uint32_t)__cvta_generic_to_shared(smem);

    const int tid  = threadIdx.x;
    const int lane = tid & 31;
    const int wid  = tid >> 5;
    const int wm = (wid & 1) * 64;
    const int wn = (wid >> 1) * 32;
    const int rowBase = blockIdx.y * 128;
    const int colBase = blockIdx.x * 128;

    const int lrow  = lane & 15;
    const int lcolA = (lane >> 4) * 8;
    const uint32_t aFragOff = (uint32_t)((wm + lrow) * 80 + lcolA * 2);
    const uint32_t bFragOff = (uint32_t)(10240 + lrow * 272 + wn * 2);

    // cp.async chunk mapping (2 chunks each for A and B per thread)
    // A: chunk id = tid*2+i ; row = id>>2 (0..127), c = id&3 (16B units)
    // B: chunk id = tid*2+i ; row = id>>4 (0..31),  c = id&15
    const int T = (3 * K) >> 5;

    float acc[4][4][4];
#pragma unroll
    for (int i = 0; i < 4; i++)
#pragma unroll
        for (int j = 0; j < 4; j++)
#pragma unroll
            for (int r = 0; r < 4; r++) acc[i][j][r] = 0.f;

    auto loadStage = [&](int t, int stage) {
        int kp0 = t << 5;
        int aSeg = (kp0 < K) ? kp0 : kp0 - K;
        int wSeg = (kp0 < 2 * K) ? kp0 : kp0 - 2 * K;
        uint32_t sb = sdata + stage * STAGE_BYTES;
#pragma unroll
        for (int i = 0; i < 2; i++) {
            int id = tid * 2 + i;
            int r = id >> 2, c = id & 3;
            int gr = rowBase + r;
            const void* src = (const void*)(Ahl + (size_t)gr * (2 * K) + aSeg + c * 8);
            uint32_t dst = sb + r * 80 + c * 16;
            int sz = (gr < N) ? 16 : 0;
            asm volatile("cp.async.cg.shared.global [%0], [%1], 16, %2;"
                         :: "r"(dst), "l"(src), "r"(sz));
        }
#pragma unroll
        for (int i = 0; i < 2; i++) {
            int id = tid * 2 + i;
            int r = id >> 4, c = id & 15;
            const void* src = (const void*)(Whl + (size_t)(wSeg + r) * M + colBase + c * 8);
            uint32_t dst = sb + 10240 + r * 272 + c * 16;
            asm volatile("cp.async.cg.shared.global [%0], [%1], 16;"
                         :: "r"(dst), "l"(src));
        }
        asm volatile("cp.async.commit_group;" ::: "memory");
    };

    loadStage(0, 0);
    if (T > 1) loadStage(1, 1);
    else       asm volatile("cp.async.commit_group;" ::: "memory");

    for (int t = 0; t < T; t++) {
        int stage = t % 3;
        if (t + 1 < T)
            asm volatile("cp.async.wait_group 1;" ::: "memory");
        else
            asm volatile("cp.async.wait_group 0;" ::: "memory");
        __syncthreads();

        uint32_t sb = sdata + stage * STAGE_BYTES;
        uint32_t aBase = sb + aFragOff;
        uint32_t bBase = sb + bFragOff;
#pragma unroll
        for (int ks = 0; ks < 2; ks++) {
            uint32_t af[4][4];
            uint32_t bfr[4][2];
            uint32_t aB = aBase + ks * 32;
            uint32_t bB = bBase + ks * 4352;
#pragma unroll
            for (int mt = 0; mt < 4; mt++) LDSM4(af[mt], aB + mt * 1280);
#pragma unroll
            for (int nt = 0; nt < 4; nt++) LDSM2T(bfr[nt], bB + nt * 16);
#pragma unroll
            for (int mt = 0; mt < 4; mt++)
#pragma unroll
                for (int nt = 0; nt < 4; nt++)
                    MMA16816(acc[mt][nt], af[mt], bfr[nt]);
        }

        if (t + 2 < T) {
            __syncthreads();               // all warps done with stage (t+2)%3
            loadStage(t + 2, (t + 2) % 3);
        }
    }

    // epilogue
    float* Cf = (float*)Cout;
    __nv_bfloat16* Cb = (__nv_bfloat16*)Cout;
    const int mr = lane >> 2;
    const int nc = (lane & 3) * 2;

#pragma unroll
    for (int mt = 0; mt < 4; mt++) {
#pragma unroll
        for (int nt = 0; nt < 4; nt++) {
            int n0 = colBase + wn + nt * 8 + nc;
            float bb0 = bias[n0], bb1 = bias[n0 + 1];
#pragma unroll
            for (int half = 0; half < 2; half++) {
                int m = rowBase + wm + mt * 16 + mr + half * 8;
                if (m >= N) continue;
                float v0 = acc[mt][nt][half * 2 + 0] + bb0;
                float v1 = acc[mt][nt][half * 2 + 1] + bb1;
                if (MODE == 0) {
                    *reinterpret_cast<float2*>(Cf + (size_t)m * M + n0) = make_float2(v0, v1);
                } else {
                    v0 = fmaxf(v0, 0.f); v1 = fmaxf(v1, 0.f);
                    __nv_bfloat16 h0, l0, h1, l1;
                    split2(v0, h0, l0); split2(v1, h1, l1);
                    __nv_bfloat16* rp = Cb + (size_t)m * (2 * M);
                    __nv_bfloat162 hv; hv.x = h0; hv.y = h1;
                    __nv_bfloat162 lv; lv.x = l0; lv.y = l1;
                    *reinterpret_cast<__nv_bfloat162*>(rp + n0)     = hv;
                    *reinterpret_cast<__nv_bfloat162*>(rp + M + n0) = lv;
                }
            }
        }
    }
}

// ---------------------------------------------------------------------------
// softmax over groups of 16 (ATT at VOA col 768)
// ---------------------------------------------------------------------------
__global__ void softmax16_kernel(float* __restrict__ VOA)
{
    int r = blockIdx.x * blockDim.x + threadIdx.x;
    if (r >= NTOK * Hh) return;
    int n = r >> 3, h = r & 7;
    float* p = VOA + (size_t)n * MVOA + 768 + h * 16;
    float v[16], mx = -1e30f;
#pragma unroll
    for (int i = 0; i < 16; i++) { v[i] = p[i]; mx = fmaxf(mx, v[i]); }
    float s = 0.f;
#pragma unroll
    for (int i = 0; i < 16; i++) { v[i] = expf(v[i] - mx); s += v[i]; }
    float inv = 1.f / s;
#pragma unroll
    for (int i = 0; i < 16; i++) p[i] = v[i] * inv;
}

// ---------------------------------------------------------------------------
// Deformable sampling; V lives in VOA cols 0..511 (row stride 896).
// Writes ACC as bf16 hi/lo [N, 2*Dm].
// ---------------------------------------------------------------------------
__global__ void sample_kernel(const float* __restrict__ VOA, const float* __restrict__ REF,
                              __nv_bfloat16* __restrict__ ACChl)
{
    int wid = blockIdx.x * (blockDim.x / 32) + (threadIdx.x / 32);
    if (wid >= NTOK * Hh) return;
    int lane = threadIdx.x & 31;
    int n = wid / Hh;
    int h = wid % Hh;
    int b = n / LQ;

    float refx = REF[(size_t)n * 2 + 0];
    float refy = REF[(size_t)n * 2 + 1];
    const float* offp = VOA + (size_t)n * MVOA + 512;
    const float* attp = VOA + (size_t)n * MVOA + 768;

    float acc0 = 0.f, acc1 = 0.f;

#pragma unroll
    for (int s = 0; s < Ss; s++) {
        int wl = c_wl[s], hl = c_hl[s];
        int base_tok = b * LQ + c_offs[s];
        float fwl = (float)wl, fhl = (float)hl;
#pragma unroll
        for (int k = 0; k < Kk; k++) {
            float w  = attp[h * 16 + s * 4 + k];
            float ox = offp[(((h * 4 + s) * 4 + k) * 2) + 0];
            float oy = offp[(((h * 4 + s) * 4 + k) * 2) + 1];
            float x = refx * fwl + ox - 0.5f;
            float y = refy * fhl + oy - 0.5f;
            float x0f = floorf(x), y0f = floorf(y);
            int x0 = (int)x0f, y0 = (int)y0f;
            float wx1 = x - x0f, wx0 = 1.f - wx1;
            float wy1 = y - y0f, wy0 = 1.f - wy1;
#pragma unroll
            for (int c = 0; c < 4; c++) {
                int xi = x0 + (c & 1);
                int yi = y0 + (c >> 1);
                float wc = ((c & 1) ? wx1 : wx0) * ((c >> 1) ? wy1 : wy0);
                bool valid = (xi >= 0) && (xi < wl) && (yi >= 0) && (yi < hl);
                if (valid) {
                    int idx = yi * wl + xi;
                    const float* vp = VOA + ((size_t)(base_tok + idx) * MVOA + h * DHh);
                    float ww = w * wc;
                    acc0 = fmaf(ww, __ldg(vp + lane),      acc0);
                    acc1 = fmaf(ww, __ldg(vp + lane + 32), acc1);
                }
            }
        }
    }
    __nv_bfloat16 h0, l0, h1, l1;
    split2(acc0, h0, l0);
    split2(acc1, h1, l1);
    size_t base = (size_t)n * (2 * Dm) + h * DHh;
    ACChl[base + lane]           = h0;
    ACChl[base + lane + 32]      = h1;
    ACChl[base + Dm + lane]      = l0;
    ACChl[base + Dm + lane + 32] = l1;
}

// ---------------------------------------------------------------------------
// Fused residual-add + LayerNorm; optionally also emits bf16 hi/lo copy.
// ---------------------------------------------------------------------------
__global__ void add_layernorm_kernel(const float* __restrict__ A, const float* __restrict__ Bv,
                                     const float* __restrict__ g, const float* __restrict__ be,
                                     float* __restrict__ out, __nv_bfloat16* __restrict__ outhl)
{
    int n = blockIdx.x;
    int t = threadIdx.x;   // 0..127
    float v[4];
    float s = 0.f, ss = 0.f;
#pragma unroll
    for (int i = 0; i < 4; i++) {
        int d = t + i * 128;
        float x = A[(size_t)n * Dm + d] + Bv[(size_t)n * Dm + d];
        v[i] = x; s += x; ss += x * x;
    }
#pragma unroll
    for (int o = 16; o > 0; o >>= 1) {
        s  += __shfl_xor_sync(0xffffffffu, s,  o);
        ss += __shfl_xor_sync(0xffffffffu, ss, o);
    }
    __shared__ float sh[8];
    int w = t >> 5, ln = t & 31;
    if (ln == 0) { sh[w] = s; sh[4 + w] = ss; }
    __syncthreads();
    float ts  = sh[0] + sh[1] + sh[2] + sh[3];
    float tss = sh[4] + sh[5] + sh[6] + sh[7];
    float mu  = ts * (1.f / Dm);
    float var = tss * (1.f / Dm) - mu * mu;
    float inv = rsqrtf(var + 1e-5f);
#pragma unroll
    for (int i = 0; i < 4; i++) {
        int d = t + i * 128;
        float o = (v[i] - mu) * inv * g[d] + be[d];
        out[(size_t)n * Dm + d] = o;
        if (outhl) {
            __nv_bfloat16 hi, lo;
            split2(o, hi, lo);
            outhl[(size_t)n * (2 * Dm) + d]      = hi;
            outhl[(size_t)n * (2 * Dm) + Dm + d] = lo;
        }
    }
}

// ---------------------------------------------------------------------------
// Launch
// ---------------------------------------------------------------------------
extern "C" void kernel_launch(void* const* d_in, const int* in_sizes, int n_in,
                              void* d_out, int out_size)
{
    const float* srcs[4] = {nullptr, nullptr, nullptr, nullptr};
    const float* refs[4] = {nullptr, nullptr, nullptr, nullptr};
    const int src_sz[4] = {Bb * 56 * 56 * Dm, Bb * 28 * 28 * Dm, Bb * 14 * 14 * Dm, Bb * 7 * 7 * Dm};
    const int ref_sz[4] = {Bb * 56 * 56 * 2,  Bb * 28 * 28 * 2,  Bb * 14 * 14 * 2,  Bb * 7 * 7 * 2};
    for (int i = 0; i < 8; i++) {
        int sz = in_sizes[i];
        for (int l = 0; l < 4; l++) {
            if (sz == src_sz[l] && !srcs[l]) { srcs[l] = (const float*)d_in[i]; goto next; }
        }
        for (int l = 0; l < 4; l++) {
            if (sz == ref_sz[l] && !refs[l]) { refs[l] = (const float*)d_in[i]; goto next; }
        }
    next:;
    }

    const float* Wv    = (const float*)d_in[8];
    const float* bv    = (const float*)d_in[9];
    const float* Woff  = (const float*)d_in[10];
    const float* boff  = (const float*)d_in[11];
    const float* Wattn = (const float*)d_in[12];
    const float* battn = (const float*)d_in[13];
    const float* Wo    = (const float*)d_in[14];
    const float* bo    = (const float*)d_in[15];
    const float* W1    = (const float*)d_in[16];
    const float* b1    = (const float*)d_in[17];
    const float* W2    = (const float*)d_in[18];
    const float* b2    = (const float*)d_in[19];
    const float* g1    = (const float*)d_in[20];
    const float* be1   = (const float*)d_in[21];
    const float* g2    = (const float*)d_in[22];
    const float* be2   = (const float*)d_in[23];
    float* out = (float*)d_out;

    float *Q, *REF, *VOA, *A2, *X, *Y, *Wall, *ball;
    __nv_bfloat16 *Qhl, *ACChl, *Xhl, *Hbhl, *Wahl, *Wohl, *W1hl, *W2hl;
    cudaGetSymbolAddress((void**)&Q,    g_Q);
    cudaGetSymbolAddress((void**)&REF,  g_REF);
    cudaGetSymbolAddress((void**)&VOA,  g_VOA);
    cudaGetSymbolAddress((void**)&A2,   g_A2);
    cudaGetSymbolAddress((void**)&X,    g_X);
    cudaGetSymbolAddress((void**)&Y,    g_Y);
    cudaGetSymbolAddress((void**)&Wall, g_Wall);
    cudaGetSymbolAddress((void**)&ball, g_ball);
    cudaGetSymbolAddress((void**)&Qhl,  g_Qhl);
    cudaGetSymbolAddress((void**)&ACChl,g_ACChl);
    cudaGetSymbolAddress((void**)&Xhl,  g_Xhl);
    cudaGetSymbolAddress((void**)&Hbhl, g_Hbhl);
    cudaGetSymbolAddress((void**)&Wahl, g_Wahl);
    cudaGetSymbolAddress((void**)&Wohl, g_Wohl);
    cudaGetSymbolAddress((void**)&W1hl, g_W1hl);
    cudaGetSymbolAddress((void**)&W2hl, g_W2hl);

    cudaFuncSetAttribute(gemm_bf16x3_kernel<0>, cudaFuncAttributeMaxDynamicSharedMemorySize, SMEM_GEMM);
    cudaFuncSetAttribute(gemm_bf16x3_kernel<1>, cudaFuncAttributeMaxDynamicSharedMemorySize, SMEM_GEMM);

    // 1. pack + weight prep
    {
        int total = NTOK * (Dm / 4);
        pack_q_kernel<<<(total + 255) / 256, 256>>>(srcs[0], srcs[1], srcs[2], srcs[3], Q, Qhl);
        pack_ref_kernel<<<(NTOK + 255) / 256, 256>>>(refs[0], refs[1], refs[2], refs[3], REF);
        merge_w_kernel<<<(Dm * MVOA + 255) / 256, 256>>>(Wv, Woff, Wattn, bv, boff, battn, Wall, ball);
        split_w_kernel<<<(Dm * MVOA + 255) / 256, 256>>>(Wall, Wahl, Dm, MVOA);
        split_w_kernel<<<(Dm * Dm + 255) / 256, 256>>>(Wo, Wohl, Dm, Dm);
        split_w_kernel<<<(Dm * DFFm + 255) / 256, 256>>>(W1, W1hl, Dm, DFFm);
        split_w_kernel<<<(DFFm * Dm + 255) / 256, 256>>>(W2, W2hl, DFFm, Dm);
    }

    const int rowBlocks = (NTOK + 127) / 128;   // 131
    dim3 blk(256);

    // 2. VOA = Q @ [Wv|Woff|Wattn] + bias
    gemm_bf16x3_kernel<0><<<dim3(MVOA / 128, rowBlocks), blk, SMEM_GEMM>>>(Qhl, Wahl, ball, VOA, NTOK, Dm, MVOA);
    // 3. softmax
    softmax16_kernel<<<(NTOK * Hh + 255) / 256, 256>>>(VOA);
    // 4. sampling -> ACChl
    {
        int warps = NTOK * Hh;
        sample_kernel<<<(warps + 7) / 8, 256>>>(VOA, REF, ACChl);
    }
    // 5. A2 = ACC @ Wo + bo
    gemm_bf16x3_kernel<0><<<dim3(Dm / 128, rowBlocks), blk, SMEM_GEMM>>>(ACChl, Wohl, bo, A2, NTOK, Dm, Dm);
    // 6. X = LN(Q + A2)  (+ Xhl)
    add_layernorm_kernel<<<NTOK, 128>>>(Q, A2, g1, be1, X, Xhl);
    // 7. Hbhl = split(relu(X @ W1 + b1))
    gemm_bf16x3_kernel<1><<<dim3(DFFm / 128, rowBlocks), blk, SMEM_GEMM>>>(Xhl, W1hl, b1, Hbhl, NTOK, Dm, DFFm);
    // 8. Y = Hb @ W2 + b2
    gemm_bf16x3_kernel<0><<<dim3(Dm / 128, rowBlocks), blk, SMEM_GEMM>>>(Hbhl, W2hl, b2, Y, NTOK, DFFm, Dm);
    // 9. out = LN(X + Y)
    add_layernorm_kernel<<<NTOK, 128>>>(X, Y, g2, be2, out, nullptr);
}

// round 7
// speedup vs baseline: 2.3590x; 1.2086x over previous
#include <cuda_runtime.h>
#include <cuda_bf16.h>
#include <cstdint>

// ---------------------------------------------------------------------------
// Problem constants
// ---------------------------------------------------------------------------
#define Dm    512
#define Hh    8
#define DHh   64
#define DFFm  2048
#define Kk    4
#define Ss    4
#define Bb    4
#define LQ    4165
#define NTOK  (Bb * LQ)     // 16660
#define MVOA  896           // merged V(512) + OFF(256) + ATT(128)

__device__ __constant__ int c_wl[4]   = {56, 28, 14, 7};
__device__ __constant__ int c_hl[4]   = {56, 28, 14, 7};
__device__ __constant__ int c_offs[4] = {0, 3136, 3920, 4116};

// ---------------------------------------------------------------------------
// Scratch
// ---------------------------------------------------------------------------
__device__ float g_Q   [(size_t)NTOK * Dm];
__device__ float g_REF [(size_t)NTOK * 2];
__device__ float g_VOA [(size_t)NTOK * MVOA];
__device__ float g_A2  [(size_t)NTOK * Dm];
__device__ float g_X   [(size_t)NTOK * Dm];
__device__ float g_Y   [(size_t)NTOK * Dm];
__device__ float g_Wall[(size_t)Dm * MVOA];
__device__ float g_ball[MVOA];

// bf16 buffers
__device__ __nv_bfloat16 g_Qhl  [(size_t)NTOK * 2 * Dm];
__device__ __nv_bfloat16 g_ACChl[(size_t)NTOK * 2 * Dm];
__device__ __nv_bfloat16 g_Xhl  [(size_t)NTOK * 2 * Dm];
__device__ __nv_bfloat16 g_Hbb  [(size_t)NTOK * DFFm];      // plain bf16 (post-ReLU)
__device__ __nv_bfloat16 g_Wahl [(size_t)2 * Dm * MVOA];
__device__ __nv_bfloat16 g_Wohl [(size_t)2 * Dm * Dm];
__device__ __nv_bfloat16 g_W1hl [(size_t)2 * Dm * DFFm];
__device__ __nv_bfloat16 g_W2hl [(size_t)2 * DFFm * Dm];

// ---------------------------------------------------------------------------
__device__ __forceinline__ int scale_of(int p, int& loc) {
    if (p < 3136)      { loc = p;        return 0; }
    else if (p < 3920) { loc = p - 3136; return 1; }
    else if (p < 4116) { loc = p - 3920; return 2; }
    else               { loc = p - 4116; return 3; }
}
__device__ __forceinline__ void split2(float v, __nv_bfloat16& hi, __nv_bfloat16& lo) {
    hi = __float2bfloat16(v);
    lo = __float2bfloat16(v - __bfloat162float(hi));
}

// ---------------------------------------------------------------------------
// pack / weight prep
// ---------------------------------------------------------------------------
__global__ void pack_q_kernel(const float* __restrict__ s0, const float* __restrict__ s1,
                              const float* __restrict__ s2, const float* __restrict__ s3,
                              float* __restrict__ Q, __nv_bfloat16* __restrict__ Qhl)
{
    int e = blockIdx.x * blockDim.x + threadIdx.x;
    const int total = NTOK * (Dm / 4);
    if (e >= total) return;
    int n  = e >> 7;
    int d4 = e & 127;
    int b = n / LQ;
    int p = n % LQ;
    int loc;
    int l = scale_of(p, loc);
    const float* src = (l == 0) ? s0 : (l == 1) ? s1 : (l == 2) ? s2 : s3;
    int lq = c_wl[l] * c_hl[l];
    float4 v = reinterpret_cast<const float4*>(src)[(size_t)(b * lq + loc) * 128 + d4];
    reinterpret_cast<float4*>(Q)[(size_t)n * 128 + d4] = v;

    float vs[4] = {v.x, v.y, v.z, v.w};
    __nv_bfloat16 hi[4], lo[4];
#pragma unroll
    for (int i = 0; i < 4; i++) split2(vs[i], hi[i], lo[i]);
    size_t base = (size_t)n * (2 * Dm) + d4 * 4;
    *reinterpret_cast<uint2*>(Qhl + base)      = *reinterpret_cast<uint2*>(hi);
    *reinterpret_cast<uint2*>(Qhl + base + Dm) = *reinterpret_cast<uint2*>(lo);
}

__global__ void pack_ref_kernel(const float* __restrict__ r0, const float* __restrict__ r1,
                                const float* __restrict__ r2, const float* __restrict__ r3,
                                float* __restrict__ REF)
{
    int n = blockIdx.x * blockDim.x + threadIdx.x;
    if (n >= NTOK) return;
    int b = n / LQ;
    int p = n % LQ;
    int loc;
    int l = scale_of(p, loc);
    const float* src = (l == 0) ? r0 : (l == 1) ? r1 : (l == 2) ? r2 : r3;
    int lq = c_wl[l] * c_hl[l];
    REF[(size_t)n * 2 + 0] = src[(size_t)(b * lq + loc) * 2 + 0];
    REF[(size_t)n * 2 + 1] = src[(size_t)(b * lq + loc) * 2 + 1];
}

__global__ void merge_w_kernel(const float* __restrict__ Wv, const float* __restrict__ Woff,
                               const float* __restrict__ Wattn,
                               const float* __restrict__ bv, const float* __restrict__ boff,
                               const float* __restrict__ battn,
                               float* __restrict__ Wall, float* __restrict__ ball)
{
    int i = blockIdx.x * blockDim.x + threadIdx.x;
    if (i < Dm * MVOA) {
        int r = i / MVOA, c = i % MVOA;
        float w;
        if (c < 512)       w = Wv[r * 512 + c];
        else if (c < 768)  w = Woff[r * 256 + (c - 512)];
        else               w = Wattn[r * 128 + (c - 768)];
        Wall[i] = w;
    }
    if (i < MVOA)
        ball[i] = (i < 512) ? bv[i] : (i < 768) ? boff[i - 512] : battn[i - 768];
}

__global__ void split_w_kernel(const float* __restrict__ W, __nv_bfloat16* __restrict__ out,
                               int K, int M)
{
    int i = blockIdx.x * blockDim.x + threadIdx.x;
    if (i >= K * M) return;
    int k = i / M, m = i % M;
    __nv_bfloat16 hi, lo;
    split2(W[i], hi, lo);
    out[(size_t)k * M + m]       = hi;
    out[(size_t)(K + k) * M + m] = lo;
}

// ---------------------------------------------------------------------------
// bf16 split GEMM via mma.sync.m16n8k16, 4-stage cp.async pipeline.
// TERMS=3: A=[N,2K] hi|lo, K'=3K (hi*hi, hi*lo, lo*hi).
// TERMS=2: A=[N,K] plain bf16, K'=2K (a*hi, a*lo).
// 128x128x32 tiles, 8 warps (64x32). MODE 0: fp32 +bias. MODE 1: relu->bf16.
// ---------------------------------------------------------------------------
#define LDSM4(r, addr) \
    asm volatile("ldmatrix.sync.aligned.m8n8.x4.shared.b16 {%0,%1,%2,%3}, [%4];" \
                 : "=r"((r)[0]), "=r"((r)[1]), "=r"((r)[2]), "=r"((r)[3]) : "r"(addr))
#define LDSM4T(r, addr) \
    asm volatile("ldmatrix.sync.aligned.m8n8.x4.trans.shared.b16 {%0,%1,%2,%3}, [%4];" \
                 : "=r"((r)[0]), "=r"((r)[1]), "=r"((r)[2]), "=r"((r)[3]) : "r"(addr))
#define MMA16816(c, a, b) \
    asm volatile("mma.sync.aligned.m16n8k16.row.col.f32.bf16.bf16.f32 " \
                 "{%0,%1,%2,%3}, {%4,%5,%6,%7}, {%8,%9}, {%0,%1,%2,%3};" \
                 : "+f"((c)[0]), "+f"((c)[1]), "+f"((c)[2]), "+f"((c)[3]) \
                 : "r"((a)[0]), "r"((a)[1]), "r"((a)[2]), "r"((a)[3]), \
                   "r"((b)[0]), "r"((b)[1]))

#define STAGE_BYTES 18944            // 10240 (A: 128x32 @80B rows) + 8704 (B: 32x128 @272B rows)
#define SMEM_GEMM   (4 * STAGE_BYTES)

template<int MODE, int TERMS>
__global__ __launch_bounds__(256, 2)
void gemm_bf16x_kernel(const __nv_bfloat16* __restrict__ Ahl,
                       const __nv_bfloat16* __restrict__ Whl,
                       const float* __restrict__ bias, void* __restrict__ Cout,
                       int N, int K, int M)
{
    extern __shared__ char smem[];
    const uint32_t sdata = (uint32_t)__cvta_generic_to_shared(smem);

    const int tid  = threadIdx.x;
    const int lane = tid & 31;
    const int wid  = tid >> 5;
    const int wm = (wid & 1) * 64;
    const int wn = (wid >> 1) * 32;
    const int rowBase = blockIdx.y * 128;
    const int colBase = blockIdx.x * 128;
    const int strideA = (TERMS == 3) ? 2 * K : K;

    // A frag (ldmatrix x4): lanes 0..15 rows, 16..31 col+8
    const int lrowA = lane & 15;
    const int lcolA = (lane >> 4) * 8;
    const uint32_t aFragOff = (uint32_t)((wm + lrowA) * 80 + lcolA * 2);
    // B frag (ldmatrix x4 trans): grp = lane>>3 -> matrix (k-half, n-half)
    const int grp = lane >> 3;
    const int rB  = lane & 7;
    const uint32_t bFragOff = (uint32_t)(10240 + ((grp & 1) * 8 + rB) * 272 + (grp >> 1) * 16 + wn * 2);

    const int T = (TERMS * K) >> 5;

    float acc[4][4][4];
#pragma unroll
    for (int i = 0; i < 4; i++)
#pragma unroll
        for (int j = 0; j < 4; j++)
#pragma unroll
            for (int r = 0; r < 4; r++) acc[i][j][r] = 0.f;

    auto loadStage = [&](int t, int stage) {
        int kp0 = t << 5;
        int aSeg = (kp0 < K) ? kp0 : kp0 - K;
        int wSeg;
        if (TERMS == 3) wSeg = (kp0 < 2 * K) ? kp0 : kp0 - 2 * K;
        else            wSeg = kp0;
        uint32_t sb = sdata + stage * STAGE_BYTES;
#pragma unroll
        for (int i = 0; i < 2; i++) {
            int id = tid * 2 + i;
            int r = id >> 2, c = id & 3;
            int gr = rowBase + r;
            const void* src = (const void*)(Ahl + (size_t)gr * strideA + aSeg + c * 8);
            uint32_t dst = sb + r * 80 + c * 16;
            int sz = (gr < N) ? 16 : 0;
            asm volatile("cp.async.cg.shared.global [%0], [%1], 16, %2;"
                         :: "r"(dst), "l"(src), "r"(sz));
        }
#pragma unroll
        for (int i = 0; i < 2; i++) {
            int id = tid * 2 + i;
            int r = id >> 4, c = id & 15;
            const void* src = (const void*)(Whl + (size_t)(wSeg + r) * M + colBase + c * 8);
            uint32_t dst = sb + 10240 + r * 272 + c * 16;
            asm volatile("cp.async.cg.shared.global [%0], [%1], 16;"
                         :: "r"(dst), "l"(src));
        }
        asm volatile("cp.async.commit_group;" ::: "memory");
    };

    loadStage(0, 0);
    loadStage(1, 1);
    loadStage(2, 2);

    for (int t = 0; t < T; t++) {
        int rem = T - 1 - t;
        if (rem >= 2)      asm volatile("cp.async.wait_group 2;" ::: "memory");
        else if (rem == 1) asm volatile("cp.async.wait_group 1;" ::: "memory");
        else               asm volatile("cp.async.wait_group 0;" ::: "memory");
        __syncthreads();

        if (t + 3 < T) loadStage(t + 3, (t + 3) & 3);

        uint32_t sb = sdata + (t & 3) * STAGE_BYTES;
        uint32_t aBase = sb + aFragOff;
        uint32_t bBase = sb + bFragOff;
#pragma unroll
        for (int ks = 0; ks < 2; ks++) {
            uint32_t af[4][4];
            uint32_t bfr[4][2];
            uint32_t aB = aBase + ks * 32;
            uint32_t bB = bBase + ks * 4352;
#pragma unroll
            for (int mt = 0; mt < 4; mt++) LDSM4(af[mt], aB + mt * 1280);
#pragma unroll
            for (int np = 0; np < 2; np++) {
                uint32_t r4[4];
                LDSM4T(r4, bB + np * 32);
                bfr[np * 2][0] = r4[0]; bfr[np * 2][1] = r4[1];
                bfr[np * 2 + 1][0] = r4[2]; bfr[np * 2 + 1][1] = r4[3];
            }
#pragma unroll
            for (int mt = 0; mt < 4; mt++)
#pragma unroll
                for (int nt = 0; nt < 4; nt++)
                    MMA16816(acc[mt][nt], af[mt], bfr[nt]);
        }
    }

    // epilogue
    float* Cf = (float*)Cout;
    __nv_bfloat16* Cb = (__nv_bfloat16*)Cout;
    const int mr = lane >> 2;
    const int nc = (lane & 3) * 2;

#pragma unroll
    for (int mt = 0; mt < 4; mt++) {
#pragma unroll
        for (int nt = 0; nt < 4; nt++) {
            int n0 = colBase + wn + nt * 8 + nc;
            float bb0 = bias[n0], bb1 = bias[n0 + 1];
#pragma unroll
            for (int half = 0; half < 2; half++) {
                int m = rowBase + wm + mt * 16 + mr + half * 8;
                if (m >= N) continue;
                float v0 = acc[mt][nt][half * 2 + 0] + bb0;
                float v1 = acc[mt][nt][half * 2 + 1] + bb1;
                if (MODE == 0) {
                    *reinterpret_cast<float2*>(Cf + (size_t)m * M + n0) = make_float2(v0, v1);
                } else {
                    v0 = fmaxf(v0, 0.f); v1 = fmaxf(v1, 0.f);
                    __nv_bfloat162 hv;
                    hv.x = __float2bfloat16(v0);
                    hv.y = __float2bfloat16(v1);
                    *reinterpret_cast<__nv_bfloat162*>(Cb + (size_t)m * M + n0) = hv;
                }
            }
        }
    }
}

// ---------------------------------------------------------------------------
// softmax over groups of 16 (ATT at VOA col 768)
// ---------------------------------------------------------------------------
__global__ void softmax16_kernel(float* __restrict__ VOA)
{
    int r = blockIdx.x * blockDim.x + threadIdx.x;
    if (r >= NTOK * Hh) return;
    int n = r >> 3, h = r & 7;
    float* p = VOA + (size_t)n * MVOA + 768 + h * 16;
    float v[16], mx = -1e30f;
#pragma unroll
    for (int i = 0; i < 16; i++) { v[i] = p[i]; mx = fmaxf(mx, v[i]); }
    float s = 0.f;
#pragma unroll
    for (int i = 0; i < 16; i++) { v[i] = expf(v[i] - mx); s += v[i]; }
    float inv = 1.f / s;
#pragma unroll
    for (int i = 0; i < 16; i++) p[i] = v[i] * inv;
}

// ---------------------------------------------------------------------------
// Deformable sampling; V in VOA cols 0..511 (row stride 896). ACC bf16 hi/lo.
// ---------------------------------------------------------------------------
__global__ void sample_kernel(const float* __restrict__ VOA, const float* __restrict__ REF,
                              __nv_bfloat16* __restrict__ ACChl)
{
    int wid = blockIdx.x * (blockDim.x / 32) + (threadIdx.x / 32);
    if (wid >= NTOK * Hh) return;
    int lane = threadIdx.x & 31;
    int n = wid / Hh;
    int h = wid % Hh;
    int b = n / LQ;

    float refx = REF[(size_t)n * 2 + 0];
    float refy = REF[(size_t)n * 2 + 1];
    const float* offp = VOA + (size_t)n * MVOA + 512;
    const float* attp = VOA + (size_t)n * MVOA + 768;

    float acc0 = 0.f, acc1 = 0.f;

#pragma unroll
    for (int s = 0; s < Ss; s++) {
        int wl = c_wl[s], hl = c_hl[s];
        int base_tok = b * LQ + c_offs[s];
        float fwl = (float)wl, fhl = (float)hl;
#pragma unroll
        for (int k = 0; k < Kk; k++) {
            float w  = attp[h * 16 + s * 4 + k];
            float ox = offp[(((h * 4 + s) * 4 + k) * 2) + 0];
            float oy = offp[(((h * 4 + s) * 4 + k) * 2) + 1];
            float x = refx * fwl + ox - 0.5f;
            float y = refy * fhl + oy - 0.5f;
            float x0f = floorf(x), y0f = floorf(y);
            int x0 = (int)x0f, y0 = (int)y0f;
            float wx1 = x - x0f, wx0 = 1.f - wx1;
            float wy1 = y - y0f, wy0 = 1.f - wy1;
#pragma unroll
            for (int c = 0; c < 4; c++) {
                int xi = x0 + (c & 1);
                int yi = y0 + (c >> 1);
                float wc = ((c & 1) ? wx1 : wx0) * ((c >> 1) ? wy1 : wy0);
                bool valid = (xi >= 0) && (xi < wl) && (yi >= 0) && (yi < hl);
                if (valid) {
                    int idx = yi * wl + xi;
                    const float* vp = VOA + ((size_t)(base_tok + idx) * MVOA + h * DHh);
                    float ww = w * wc;
                    acc0 = fmaf(ww, __ldg(vp + lane),      acc0);
                    acc1 = fmaf(ww, __ldg(vp + lane + 32), acc1);
                }
            }
        }
    }
    __nv_bfloat16 h0, l0, h1, l1;
    split2(acc0, h0, l0);
    split2(acc1, h1, l1);
    size_t base = (size_t)n * (2 * Dm) + h * DHh;
    ACChl[base + lane]           = h0;
    ACChl[base + lane + 32]      = h1;
    ACChl[base + Dm + lane]      = l0;
    ACChl[base + Dm + lane + 32] = l1;
}

// ---------------------------------------------------------------------------
// Fused residual-add + LayerNorm; optionally emits bf16 hi/lo copy.
// ---------------------------------------------------------------------------
__global__ void add_layernorm_kernel(const float* __restrict__ A, const float* __restrict__ Bv,
                                     const float* __restrict__ g, const float* __restrict__ be,
                                     float* __restrict__ out, __nv_bfloat16* __restrict__ outhl)
{
    int n = blockIdx.x;
    int t = threadIdx.x;
    float v[4];
    float s = 0.f, ss = 0.f;
#pragma unroll
    for (int i = 0; i < 4; i++) {
        int d = t + i * 128;
        float x = A[(size_t)n * Dm + d] + Bv[(size_t)n * Dm + d];
        v[i] = x; s += x; ss += x * x;
    }
#pragma unroll
    for (int o = 16; o > 0; o >>= 1) {
        s  += __shfl_xor_sync(0xffffffffu, s,  o);
        ss += __shfl_xor_sync(0xffffffffu, ss, o);
    }
    __shared__ float sh[8];
    int w = t >> 5, ln = t & 31;
    if (ln == 0) { sh[w] = s; sh[4 + w] = ss; }
    __syncthreads();
    float ts  = sh[0] + sh[1] + sh[2] + sh[3];
    float tss = sh[4] + sh[5] + sh[6] + sh[7];
    float mu  = ts * (1.f / Dm);
    float var = tss * (1.f / Dm) - mu * mu;
    float inv = rsqrtf(var + 1e-5f);
#pragma unroll
    for (int i = 0; i < 4; i++) {
        int d = t + i * 128;
        float o = (v[i] - mu) * inv * g[d] + be[d];
        out[(size_t)n * Dm + d] = o;
        if (outhl) {
            __nv_bfloat16 hi, lo;
            split2(o, hi, lo);
            outhl[(size_t)n * (2 * Dm) + d]      = hi;
            outhl[(size_t)n * (2 * Dm) + Dm + d] = lo;
        }
    }
}

// ---------------------------------------------------------------------------
// Launch
// ---------------------------------------------------------------------------
extern "C" void kernel_launch(void* const* d_in, const int* in_sizes, int n_in,
                              void* d_out, int out_size)
{
    const float* srcs[4] = {nullptr, nullptr, nullptr, nullptr};
    const float* refs[4] = {nullptr, nullptr, nullptr, nullptr};
    const int src_sz[4] = {Bb * 56 * 56 * Dm, Bb * 28 * 28 * Dm, Bb * 14 * 14 * Dm, Bb * 7 * 7 * Dm};
    const int ref_sz[4] = {Bb * 56 * 56 * 2,  Bb * 28 * 28 * 2,  Bb * 14 * 14 * 2,  Bb * 7 * 7 * 2};
    for (int i = 0; i < 8; i++) {
        int sz = in_sizes[i];
        for (int l = 0; l < 4; l++) {
            if (sz == src_sz[l] && !srcs[l]) { srcs[l] = (const float*)d_in[i]; goto next; }
        }
        for (int l = 0; l < 4; l++) {
            if (sz == ref_sz[l] && !refs[l]) { refs[l] = (const float*)d_in[i]; goto next; }
        }
    next:;
    }

    const float* Wv    = (const float*)d_in[8];
    const float* bv    = (const float*)d_in[9];
    const float* Woff  = (const float*)d_in[10];
    const float* boff  = (const float*)d_in[11];
    const float* Wattn = (const float*)d_in[12];
    const float* battn = (const float*)d_in[13];
    const float* Wo    = (const float*)d_in[14];
    const float* bo    = (const float*)d_in[15];
    const float* W1    = (const float*)d_in[16];
    const float* b1    = (const float*)d_in[17];
    const float* W2    = (const float*)d_in[18];
    const float* b2    = (const float*)d_in[19];
    const float* g1    = (const float*)d_in[20];
    const float* be1   = (const float*)d_in[21];
    const float* g2    = (const float*)d_in[22];
    const float* be2   = (const float*)d_in[23];
    float* out = (float*)d_out;

    float *Q, *REF, *VOA, *A2, *X, *Y, *Wall, *ball;
    __nv_bfloat16 *Qhl, *ACChl, *Xhl, *Hbb, *Wahl, *Wohl, *W1hl, *W2hl;
    cudaGetSymbolAddress((void**)&Q,    g_Q);
    cudaGetSymbolAddress((void**)&REF,  g_REF);
    cudaGetSymbolAddress((void**)&VOA,  g_VOA);
    cudaGetSymbolAddress((void**)&A2,   g_A2);
    cudaGetSymbolAddress((void**)&X,    g_X);
    cudaGetSymbolAddress((void**)&Y,    g_Y);
    cudaGetSymbolAddress((void**)&Wall, g_Wall);
    cudaGetSymbolAddress((void**)&ball, g_ball);
    cudaGetSymbolAddress((void**)&Qhl,  g_Qhl);
    cudaGetSymbolAddress((void**)&ACChl,g_ACChl);
    cudaGetSymbolAddress((void**)&Xhl,  g_Xhl);
    cudaGetSymbolAddress((void**)&Hbb,  g_Hbb);
    cudaGetSymbolAddress((void**)&Wahl, g_Wahl);
    cudaGetSymbolAddress((void**)&Wohl, g_Wohl);
    cudaGetSymbolAddress((void**)&W1hl, g_W1hl);
    cudaGetSymbolAddress((void**)&W2hl, g_W2hl);

    cudaFuncSetAttribute(gemm_bf16x_kernel<0,3>, cudaFuncAttributeMaxDynamicSharedMemorySize, SMEM_GEMM);
    cudaFuncSetAttribute(gemm_bf16x_kernel<1,3>, cudaFuncAttributeMaxDynamicSharedMemorySize, SMEM_GEMM);
    cudaFuncSetAttribute(gemm_bf16x_kernel<0,2>, cudaFuncAttributeMaxDynamicSharedMemorySize, SMEM_GEMM);

    // 1. pack + weight prep
    {
        int total = NTOK * (Dm / 4);
        pack_q_kernel<<<(total + 255) / 256, 256>>>(srcs[0], srcs[1], srcs[2], srcs[3], Q, Qhl);
        pack_ref_kernel<<<(NTOK + 255) / 256, 256>>>(refs[0], refs[1], refs[2], refs[3], REF);
        merge_w_kernel<<<(Dm * MVOA + 255) / 256, 256>>>(Wv, Woff, Wattn, bv, boff, battn, Wall, ball);
        split_w_kernel<<<(Dm * MVOA + 255) / 256, 256>>>(Wall, Wahl, Dm, MVOA);
        split_w_kernel<<<(Dm * Dm + 255) / 256, 256>>>(Wo, Wohl, Dm, Dm);
        split_w_kernel<<<(Dm * DFFm + 255) / 256, 256>>>(W1, W1hl, Dm, DFFm);
        split_w_kernel<<<(DFFm * Dm + 255) / 256, 256>>>(W2, W2hl, DFFm, Dm);
    }

    const int rowBlocks = (NTOK + 127) / 128;   // 131
    dim3 blk(256);

    // 2. VOA = Q @ [Wv|Woff|Wattn] + bias   (bf16x3)
    gemm_bf16x_kernel<0,3><<<dim3(MVOA / 128, rowBlocks), blk, SMEM_GEMM>>>(Qhl, Wahl, ball, VOA, NTOK, Dm, MVOA);
    // 3. softmax
    softmax16_kernel<<<(NTOK * Hh + 255) / 256, 256>>>(VOA);
    // 4. sampling -> ACChl
    {
        int warps = NTOK * Hh;
        sample_kernel<<<(warps + 7) / 8, 256>>>(VOA, REF, ACChl);
    }
    // 5. A2 = ACC @ Wo + bo   (bf16x3)
    gemm_bf16x_kernel<0,3><<<dim3(Dm / 128, rowBlocks), blk, SMEM_GEMM>>>(ACChl, Wohl, bo, A2, NTOK, Dm, Dm);
    // 6. X = LN(Q + A2)  (+ Xhl)
    add_layernorm_kernel<<<NTOK, 128>>>(Q, A2, g1, be1, X, Xhl);
    // 7. Hbb = bf16(relu(X @ W1 + b1))   (bf16x3, bf16 out)
    gemm_bf16x_kernel<1,3><<<dim3(DFFm / 128, rowBlocks), blk, SMEM_GEMM>>>(Xhl, W1hl, b1, Hbb, NTOK, Dm, DFFm);
    // 8. Y = Hb @ W2 + b2   (bf16x2: A plain bf16, W hi+lo)
    gemm_bf16x_kernel<0,2><<<dim3(Dm / 128, rowBlocks), blk, SMEM_GEMM>>>(Hbb, W2hl, b2, Y, NTOK, DFFm, Dm);
    // 9. out = LN(X + Y)
    add_layernorm_kernel<<<NTOK, 128>>>(X, Y, g2, be2, out, nullptr);
}

// round 8
// speedup vs baseline: 2.8607x; 1.2127x over previous
#include <cuda_runtime.h>
#include <cuda_fp16.h>
#include <cstdint>

// ---------------------------------------------------------------------------
// Problem constants
// ---------------------------------------------------------------------------
#define Dm    512
#define Hh    8
#define DHh   64
#define DFFm  2048
#define Kk    4
#define Ss    4
#define Bb    4
#define LQ    4165
#define NTOK  (Bb * LQ)     // 16660
#define MVOA  896           // merged V(512) + OFF(256) + ATT(128)

__device__ __constant__ int c_wl[4]   = {56, 28, 14, 7};
__device__ __constant__ int c_hl[4]   = {56, 28, 14, 7};
__device__ __constant__ int c_offs[4] = {0, 3136, 3920, 4116};

// ---------------------------------------------------------------------------
// Scratch
// ---------------------------------------------------------------------------
__device__ float g_Q   [(size_t)NTOK * Dm];
__device__ float g_REF [(size_t)NTOK * 2];
__device__ float g_VOA [(size_t)NTOK * MVOA];
__device__ float g_A2  [(size_t)NTOK * Dm];
__device__ float g_X   [(size_t)NTOK * Dm];
__device__ float g_Y   [(size_t)NTOK * Dm];
__device__ float g_ball[MVOA];

// fp16 buffers: activations [N,K] single; weights [2K,M] = hi rows then lo rows
__device__ __half g_Qh  [(size_t)NTOK * Dm];
__device__ __half g_ACCh[(size_t)NTOK * Dm];
__device__ __half g_Xh  [(size_t)NTOK * Dm];
__device__ __half g_Hbh [(size_t)NTOK * DFFm];
__device__ __half g_Wah [(size_t)2 * Dm * MVOA];
__device__ __half g_Woh [(size_t)2 * Dm * Dm];
__device__ __half g_W1h [(size_t)2 * Dm * DFFm];
__device__ __half g_W2h [(size_t)2 * DFFm * Dm];

// ---------------------------------------------------------------------------
__device__ __forceinline__ int scale_of(int p, int& loc) {
    if (p < 3136)      { loc = p;        return 0; }
    else if (p < 3920) { loc = p - 3136; return 1; }
    else if (p < 4116) { loc = p - 3920; return 2; }
    else               { loc = p - 4116; return 3; }
}
__device__ __forceinline__ void splitH(float v, __half& hi, __half& lo) {
    hi = __float2half(v);
    lo = __float2half(v - __half2float(hi));
}

// ---------------------------------------------------------------------------
// pack: srcs -> Q fp32 + Qh fp16; refs -> REF
// ---------------------------------------------------------------------------
__global__ void pack_q_kernel(const float* __restrict__ s0, const float* __restrict__ s1,
                              const float* __restrict__ s2, const float* __restrict__ s3,
                              float* __restrict__ Q, __half* __restrict__ Qh)
{
    int e = blockIdx.x * blockDim.x + threadIdx.x;
    const int total = NTOK * (Dm / 4);
    if (e >= total) return;
    int n  = e >> 7;
    int d4 = e & 127;
    int b = n / LQ;
    int p = n % LQ;
    int loc;
    int l = scale_of(p, loc);
    const float* src = (l == 0) ? s0 : (l == 1) ? s1 : (l == 2) ? s2 : s3;
    int lq = c_wl[l] * c_hl[l];
    float4 v = reinterpret_cast<const float4*>(src)[(size_t)(b * lq + loc) * 128 + d4];
    reinterpret_cast<float4*>(Q)[(size_t)n * 128 + d4] = v;

    __half h[4] = {__float2half(v.x), __float2half(v.y), __float2half(v.z), __float2half(v.w)};
    *reinterpret_cast<uint2*>(Qh + (size_t)n * Dm + d4 * 4) = *reinterpret_cast<uint2*>(h);
}

__global__ void pack_ref_kernel(const float* __restrict__ r0, const float* __restrict__ r1,
                                const float* __restrict__ r2, const float* __restrict__ r3,
                                float* __restrict__ REF)
{
    int n = blockIdx.x * blockDim.x + threadIdx.x;
    if (n >= NTOK) return;
    int b = n / LQ;
    int p = n % LQ;
    int loc;
    int l = scale_of(p, loc);
    const float* src = (l == 0) ? r0 : (l == 1) ? r1 : (l == 2) ? r2 : r3;
    int lq = c_wl[l] * c_hl[l];
    REF[(size_t)n * 2 + 0] = src[(size_t)(b * lq + loc) * 2 + 0];
    REF[(size_t)n * 2 + 1] = src[(size_t)(b * lq + loc) * 2 + 1];
}

// merge Wv/Woff/Wattn -> fp16 hi/lo [2*512, 896] directly (+ merged bias)
__global__ void merge_split_kernel(const float* __restrict__ Wv, const float* __restrict__ Woff,
                                   const float* __restrict__ Wattn,
                                   const float* __restrict__ bv, const float* __restrict__ boff,
                                   const float* __restrict__ battn,
                                   __half* __restrict__ Wah, float* __restrict__ ball)
{
    int i = blockIdx.x * blockDim.x + threadIdx.x;
    if (i < Dm * MVOA) {
        int r = i / MVOA, c = i % MVOA;
        float w;
        if (c < 512)       w = Wv[r * 512 + c];
        else if (c < 768)  w = Woff[r * 256 + (c - 512)];
        else               w = Wattn[r * 128 + (c - 768)];
        __half hi, lo;
        splitH(w, hi, lo);
        Wah[(size_t)r * MVOA + c]        = hi;
        Wah[(size_t)(Dm + r) * MVOA + c] = lo;
    }
    if (i < MVOA)
        ball[i] = (i < 512) ? bv[i] : (i < 768) ? boff[i - 512] : battn[i - 768];
}

// split fp32 weight [K,M] -> fp16 [2K,M]
__global__ void split_w_kernel(const float* __restrict__ W, __half* __restrict__ out,
                               int K, int M)
{
    int i = blockIdx.x * blockDim.x + threadIdx.x;
    if (i >= K * M) return;
    int k = i / M, m = i % M;
    __half hi, lo;
    splitH(W[i], hi, lo);
    out[(size_t)k * M + m]       = hi;
    out[(size_t)(K + k) * M + m] = lo;
}

// ---------------------------------------------------------------------------
// fp16 2-term GEMM via mma.sync.m16n8k16.f32.f16.f16.f32, 4-stage cp.async.
//   C[N,M] = A[N,K](fp16) x (Whi + Wlo)  + bias      (logical K' = 2K)
// W stored [2K,M]: rows 0..K-1 hi, K..2K-1 lo; k'-row maps directly.
// 128x128x32 tiles, 8 warps (64x32). MODE 0: fp32 +bias. MODE 1: relu->fp16.
// ---------------------------------------------------------------------------
#define LDSM4(r, addr) \
    asm volatile("ldmatrix.sync.aligned.m8n8.x4.shared.b16 {%0,%1,%2,%3}, [%4];" \
                 : "=r"((r)[0]), "=r"((r)[1]), "=r"((r)[2]), "=r"((r)[3]) : "r"(addr))
#define LDSM4T(r, addr) \
    asm volatile("ldmatrix.sync.aligned.m8n8.x4.trans.shared.b16 {%0,%1,%2,%3}, [%4];" \
                 : "=r"((r)[0]), "=r"((r)[1]), "=r"((r)[2]), "=r"((r)[3]) : "r"(addr))
#define MMA16816H(c, a, b) \
    asm volatile("mma.sync.aligned.m16n8k16.row.col.f32.f16.f16.f32 " \
                 "{%0,%1,%2,%3}, {%4,%5,%6,%7}, {%8,%9}, {%0,%1,%2,%3};" \
                 : "+f"((c)[0]), "+f"((c)[1]), "+f"((c)[2]), "+f"((c)[3]) \
                 : "r"((a)[0]), "r"((a)[1]), "r"((a)[2]), "r"((a)[3]), \
                   "r"((b)[0]), "r"((b)[1]))

#define STAGE_BYTES 18944            // 10240 (A: 128x32 @80B rows) + 8704 (B: 32x128 @272B rows)
#define SMEM_GEMM   (4 * STAGE_BYTES)

template<int MODE>
__global__ __launch_bounds__(256, 2)
void gemm_fp16x2_kernel(const __half* __restrict__ A,
                        const __half* __restrict__ Whl,
                        const float* __restrict__ bias, void* __restrict__ Cout,
                        int N, int K, int M)
{
    extern __shared__ char smem[];
    const uint32_t sdata = (uint32_t)__cvta_generic_to_shared(smem);

    const int tid  = threadIdx.x;
    const int lane = tid & 31;
    const int wid  = tid >> 5;
    const int wm = (wid & 1) * 64;
    const int wn = (wid >> 1) * 32;
    const int rowBase = blockIdx.y * 128;
    const int colBase = blockIdx.x * 128;

    const int lrowA = lane & 15;
    const int lcolA = (lane >> 4) * 8;
    const uint32_t aFragOff = (uint32_t)((wm + lrowA) * 80 + lcolA * 2);
    const int grp = lane >> 3;
    const int rB  = lane & 7;
    const uint32_t bFragOff = (uint32_t)(10240 + ((grp & 1) * 8 + rB) * 272 + (grp >> 1) * 16 + wn * 2);

    const int T = (2 * K) >> 5;

    float acc[4][4][4];
#pragma unroll
    for (int i = 0; i < 4; i++)
#pragma unroll
        for (int j = 0; j < 4; j++)
#pragma unroll
            for (int r = 0; r < 4; r++) acc[i][j][r] = 0.f;

    auto loadStage = [&](int t, int stage) {
        int kp0 = t << 5;
        int aSeg = (kp0 < K) ? kp0 : kp0 - K;   // A repeats for lo segment
        int wSeg = kp0;                         // W rows map directly [2K,M]
        uint32_t sb = sdata + stage * STAGE_BYTES;
#pragma unroll
        for (int i = 0; i < 2; i++) {
            int id = tid * 2 + i;
            int r = id >> 2, c = id & 3;
            int gr = rowBase + r;
            const void* src = (const void*)(A + (size_t)gr * K + aSeg + c * 8);
            uint32_t dst = sb + r * 80 + c * 16;
            int sz = (gr < N) ? 16 : 0;
            asm volatile("cp.async.cg.shared.global [%0], [%1], 16, %2;"
                         :: "r"(dst), "l"(src), "r"(sz));
        }
#pragma unroll
        for (int i = 0; i < 2; i++) {
            int id = tid * 2 + i;
            int r = id >> 4, c = id & 15;
            const void* src = (const void*)(Whl + (size_t)(wSeg + r) * M + colBase + c * 8);
            uint32_t dst = sb + 10240 + r * 272 + c * 16;
            asm volatile("cp.async.cg.shared.global [%0], [%1], 16;"
                         :: "r"(dst), "l"(src));
        }
        asm volatile("cp.async.commit_group;" ::: "memory");
    };

    loadStage(0, 0);
    loadStage(1, 1);
    loadStage(2, 2);

    for (int t = 0; t < T; t++) {
        int rem = T - 1 - t;
        if (rem >= 2)      asm volatile("cp.async.wait_group 2;" ::: "memory");
        else if (rem == 1) asm volatile("cp.async.wait_group 1;" ::: "memory");
        else               asm volatile("cp.async.wait_group 0;" ::: "memory");
        __syncthreads();

        if (t + 3 < T) loadStage(t + 3, (t + 3) & 3);

        uint32_t sb = sdata + (t & 3) * STAGE_BYTES;
        uint32_t aBase = sb + aFragOff;
        uint32_t bBase = sb + bFragOff;
#pragma unroll
        for (int ks = 0; ks < 2; ks++) {
            uint32_t af[4][4];
            uint32_t bfr[4][2];
            uint32_t aB = aBase + ks * 32;
            uint32_t bB = bBase + ks * 4352;
#pragma unroll
            for (int mt = 0; mt < 4; mt++) LDSM4(af[mt], aB + mt * 1280);
#pragma unroll
            for (int np = 0; np < 2; np++) {
                uint32_t r4[4];
                LDSM4T(r4, bB + np * 32);
                bfr[np * 2][0] = r4[0]; bfr[np * 2][1] = r4[1];
                bfr[np * 2 + 1][0] = r4[2]; bfr[np * 2 + 1][1] = r4[3];
            }
#pragma unroll
            for (int mt = 0; mt < 4; mt++)
#pragma unroll
                for (int nt = 0; nt < 4; nt++)
                    MMA16816H(acc[mt][nt], af[mt], bfr[nt]);
        }
    }

    // epilogue
    float* Cf = (float*)Cout;
    __half* Ch = (__half*)Cout;
    const int mr = lane >> 2;
    const int nc = (lane & 3) * 2;

#pragma unroll
    for (int mt = 0; mt < 4; mt++) {
#pragma unroll
        for (int nt = 0; nt < 4; nt++) {
            int n0 = colBase + wn + nt * 8 + nc;
            float bb0 = bias[n0], bb1 = bias[n0 + 1];
#pragma unroll
            for (int half = 0; half < 2; half++) {
                int m = rowBase + wm + mt * 16 + mr + half * 8;
                if (m >= N) continue;
                float v0 = acc[mt][nt][half * 2 + 0] + bb0;
                float v1 = acc[mt][nt][half * 2 + 1] + bb1;
                if (MODE == 0) {
                    *reinterpret_cast<float2*>(Cf + (size_t)m * M + n0) = make_float2(v0, v1);
                } else {
                    v0 = fmaxf(v0, 0.f); v1 = fmaxf(v1, 0.f);
                    __half2 hv;
                    hv.x = __float2half(v0);
                    hv.y = __float2half(v1);
                    *reinterpret_cast<__half2*>(Ch + (size_t)m * M + n0) = hv;
                }
            }
        }
    }
}

// ---------------------------------------------------------------------------
// softmax over groups of 16 (ATT at VOA col 768)
// ---------------------------------------------------------------------------
__global__ void softmax16_kernel(float* __restrict__ VOA)
{
    int r = blockIdx.x * blockDim.x + threadIdx.x;
    if (r >= NTOK * Hh) return;
    int n = r >> 3, h = r & 7;
    float* p = VOA + (size_t)n * MVOA + 768 + h * 16;
    float v[16], mx = -1e30f;
#pragma unroll
    for (int i = 0; i < 16; i++) { v[i] = p[i]; mx = fmaxf(mx, v[i]); }
    float s = 0.f;
#pragma unroll
    for (int i = 0; i < 16; i++) { v[i] = expf(v[i] - mx); s += v[i]; }
    float inv = 1.f / s;
#pragma unroll
    for (int i = 0; i < 16; i++) p[i] = v[i] * inv;
}

// ---------------------------------------------------------------------------
// Deformable sampling; V in VOA cols 0..511 (row stride 896). ACC fp16.
// ---------------------------------------------------------------------------
__global__ void sample_kernel(const float* __restrict__ VOA, const float* __restrict__ REF,
                              __half* __restrict__ ACCh)
{
    int wid = blockIdx.x * (blockDim.x / 32) + (threadIdx.x / 32);
    if (wid >= NTOK * Hh) return;
    int lane = threadIdx.x & 31;
    int n = wid / Hh;
    int h = wid % Hh;
    int b = n / LQ;

    float refx = REF[(size_t)n * 2 + 0];
    float refy = REF[(size_t)n * 2 + 1];
    const float* offp = VOA + (size_t)n * MVOA + 512;
    const float* attp = VOA + (size_t)n * MVOA + 768;

    float acc0 = 0.f, acc1 = 0.f;

#pragma unroll
    for (int s = 0; s < Ss; s++) {
        int wl = c_wl[s], hl = c_hl[s];
        int base_tok = b * LQ + c_offs[s];
        float fwl = (float)wl, fhl = (float)hl;
#pragma unroll
        for (int k = 0; k < Kk; k++) {
            float w  = attp[h * 16 + s * 4 + k];
            float ox = offp[(((h * 4 + s) * 4 + k) * 2) + 0];
            float oy = offp[(((h * 4 + s) * 4 + k) * 2) + 1];
            float x = refx * fwl + ox - 0.5f;
            float y = refy * fhl + oy - 0.5f;
            float x0f = floorf(x), y0f = floorf(y);
            int x0 = (int)x0f, y0 = (int)y0f;
            float wx1 = x - x0f, wx0 = 1.f - wx1;
            float wy1 = y - y0f, wy0 = 1.f - wy1;
#pragma unroll
            for (int c = 0; c < 4; c++) {
                int xi = x0 + (c & 1);
                int yi = y0 + (c >> 1);
                float wc = ((c & 1) ? wx1 : wx0) * ((c >> 1) ? wy1 : wy0);
                bool valid = (xi >= 0) && (xi < wl) && (yi >= 0) && (yi < hl);
                if (valid) {
                    int idx = yi * wl + xi;
                    const float* vp = VOA + ((size_t)(base_tok + idx) * MVOA + h * DHh);
                    float ww = w * wc;
                    acc0 = fmaf(ww, __ldg(vp + lane),      acc0);
                    acc1 = fmaf(ww, __ldg(vp + lane + 32), acc1);
                }
            }
        }
    }
    size_t base = (size_t)n * Dm + h * DHh;
    ACCh[base + lane]      = __float2half(acc0);
    ACCh[base + lane + 32] = __float2half(acc1);
}

// ---------------------------------------------------------------------------
// Fused residual-add + LayerNorm; optionally emits fp16 copy.
// ---------------------------------------------------------------------------
__global__ void add_layernorm_kernel(const float* __restrict__ A, const float* __restrict__ Bv,
                                     const float* __restrict__ g, const float* __restrict__ be,
                                     float* __restrict__ out, __half* __restrict__ outh)
{
    int n = blockIdx.x;
    int t = threadIdx.x;
    float v[4];
    float s = 0.f, ss = 0.f;
#pragma unroll
    for (int i = 0; i < 4; i++) {
        int d = t + i * 128;
        float x = A[(size_t)n * Dm + d] + Bv[(size_t)n * Dm + d];
        v[i] = x; s += x; ss += x * x;
    }
#pragma unroll
    for (int o = 16; o > 0; o >>= 1) {
        s  += __shfl_xor_sync(0xffffffffu, s,  o);
        ss += __shfl_xor_sync(0xffffffffu, ss, o);
    }
    __shared__ float sh[8];
    int w = t >> 5, ln = t & 31;
    if (ln == 0) { sh[w] = s; sh[4 + w] = ss; }
    __syncthreads();
    float ts  = sh[0] + sh[1] + sh[2] + sh[3];
    float tss = sh[4] + sh[5] + sh[6] + sh[7];
    float mu  = ts * (1.f / Dm);
    float var = tss * (1.f / Dm) - mu * mu;
    float inv = rsqrtf(var + 1e-5f);
#pragma unroll
    for (int i = 0; i < 4; i++) {
        int d = t + i * 128;
        float o = (v[i] - mu) * inv * g[d] + be[d];
        out[(size_t)n * Dm + d] = o;
        if (outh) outh[(size_t)n * Dm + d] = __float2half(o);
    }
}

// ---------------------------------------------------------------------------
// Launch
// ---------------------------------------------------------------------------
extern "C" void kernel_launch(void* const* d_in, const int* in_sizes, int n_in,
                              void* d_out, int out_size)
{
    const float* srcs[4] = {nullptr, nullptr, nullptr, nullptr};
    const float* refs[4] = {nullptr, nullptr, nullptr, nullptr};
    const int src_sz[4] = {Bb * 56 * 56 * Dm, Bb * 28 * 28 * Dm, Bb * 14 * 14 * Dm, Bb * 7 * 7 * Dm};
    const int ref_sz[4] = {Bb * 56 * 56 * 2,  Bb * 28 * 28 * 2,  Bb * 14 * 14 * 2,  Bb * 7 * 7 * 2};
    for (int i = 0; i < 8; i++) {
        int sz = in_sizes[i];
        for (int l = 0; l < 4; l++) {
            if (sz == src_sz[l] && !srcs[l]) { srcs[l] = (const float*)d_in[i]; goto next; }
        }
        for (int l = 0; l < 4; l++) {
            if (sz == ref_sz[l] && !refs[l]) { refs[l] = (const float*)d_in[i]; goto next; }
        }
    next:;
    }

    const float* Wv    = (const float*)d_in[8];
    const float* bv    = (const float*)d_in[9];
    const float* Woff  = (const float*)d_in[10];
    const float* boff  = (const float*)d_in[11];
    const float* Wattn = (const float*)d_in[12];
    const float* battn = (const float*)d_in[13];
    const float* Wo    = (const float*)d_in[14];
    const float* bo    = (const float*)d_in[15];
    const float* W1    = (const float*)d_in[16];
    const float* b1    = (const float*)d_in[17];
    const float* W2    = (const float*)d_in[18];
    const float* b2    = (const float*)d_in[19];
    const float* g1    = (const float*)d_in[20];
    const float* be1   = (const float*)d_in[21];
    const float* g2    = (const float*)d_in[22];
    const float* be2   = (const float*)d_in[23];
    float* out = (float*)d_out;

    float *Q, *REF, *VOA, *A2, *X, *Y, *ball;
    __half *Qh, *ACCh, *Xh, *Hbh, *Wah, *Woh, *W1h, *W2h;
    cudaGetSymbolAddress((void**)&Q,    g_Q);
    cudaGetSymbolAddress((void**)&REF,  g_REF);
    cudaGetSymbolAddress((void**)&VOA,  g_VOA);
    cudaGetSymbolAddress((void**)&A2,   g_A2);
    cudaGetSymbolAddress((void**)&X,    g_X);
    cudaGetSymbolAddress((void**)&Y,    g_Y);
    cudaGetSymbolAddress((void**)&ball, g_ball);
    cudaGetSymbolAddress((void**)&Qh,   g_Qh);
    cudaGetSymbolAddress((void**)&ACCh, g_ACCh);
    cudaGetSymbolAddress((void**)&Xh,   g_Xh);
    cudaGetSymbolAddress((void**)&Hbh,  g_Hbh);
    cudaGetSymbolAddress((void**)&Wah,  g_Wah);
    cudaGetSymbolAddress((void**)&Woh,  g_Woh);
    cudaGetSymbolAddress((void**)&W1h,  g_W1h);
    cudaGetSymbolAddress((void**)&W2h,  g_W2h);

    cudaFuncSetAttribute(gemm_fp16x2_kernel<0>, cudaFuncAttributeMaxDynamicSharedMemorySize, SMEM_GEMM);
    cudaFuncSetAttribute(gemm_fp16x2_kernel<1>, cudaFuncAttributeMaxDynamicSharedMemorySize, SMEM_GEMM);

    // 1. pack + weight prep
    {
        int total = NTOK * (Dm / 4);
        pack_q_kernel<<<(total + 255) / 256, 256>>>(srcs[0], srcs[1], srcs[2], srcs[3], Q, Qh);
        pack_ref_kernel<<<(NTOK + 255) / 256, 256>>>(refs[0], refs[1], refs[2], refs[3], REF);
        merge_split_kernel<<<(Dm * MVOA + 255) / 256, 256>>>(Wv, Woff, Wattn, bv, boff, battn, Wah, ball);
        split_w_kernel<<<(Dm * Dm + 255) / 256, 256>>>(Wo, Woh, Dm, Dm);
        split_w_kernel<<<(Dm * DFFm + 255) / 256, 256>>>(W1, W1h, Dm, DFFm);
        split_w_kernel<<<(DFFm * Dm + 255) / 256, 256>>>(W2, W2h, DFFm, Dm);
    }

    const int rowBlocks = (NTOK + 127) / 128;   // 131
    dim3 blk(256);

    // 2. VOA = Q @ [Wv|Woff|Wattn] + bias
    gemm_fp16x2_kernel<0><<<dim3(MVOA / 128, rowBlocks), blk, SMEM_GEMM>>>(Qh, Wah, ball, VOA, NTOK, Dm, MVOA);
    // 3. softmax
    softmax16_kernel<<<(NTOK * Hh + 255) / 256, 256>>>(VOA);
    // 4. sampling -> ACCh
    {
        int warps = NTOK * Hh;
        sample_kernel<<<(warps + 7) / 8, 256>>>(VOA, REF, ACCh);
    }
    // 5. A2 = ACC @ Wo + bo
    gemm_fp16x2_kernel<0><<<dim3(Dm / 128, rowBlocks), blk, SMEM_GEMM>>>(ACCh, Woh, bo, A2, NTOK, Dm, Dm);
    // 6. X = LN(Q + A2)  (+ Xh)
    add_layernorm_kernel<<<NTOK, 128>>>(Q, A2, g1, be1, X, Xh);
    // 7. Hbh = fp16(relu(X @ W1 + b1))
    gemm_fp16x2_kernel<1><<<dim3(DFFm / 128, rowBlocks), blk, SMEM_GEMM>>>(Xh, W1h, b1, Hbh, NTOK, Dm, DFFm);
    // 8. Y = Hb @ W2 + b2
    gemm_fp16x2_kernel<0><<<dim3(Dm / 128, rowBlocks), blk, SMEM_GEMM>>>(Hbh, W2h, b2, Y, NTOK, DFFm, Dm);
    // 9. out = LN(X + Y)
    add_layernorm_kernel<<<NTOK, 128>>>(X, Y, g2, be2, out, nullptr);
}

// round 9
// speedup vs baseline: 4.4059x; 1.5402x over previous
#include <cuda_runtime.h>
#include <cuda_fp16.h>
#include <cstdint>

// ---------------------------------------------------------------------------
// Problem constants
// ---------------------------------------------------------------------------
#define Dm    512
#define Hh    8
#define DHh   64
#define DFFm  2048
#define Kk    4
#define Ss    4
#define Bb    4
#define LQ    4165
#define NTOK  (Bb * LQ)     // 16660
#define MVOA  896           // merged V(512) + OFF(256) + ATT(128)
#define MOA2  384           // OFF+ATT width

__device__ __constant__ int c_wl[4]   = {56, 28, 14, 7};
__device__ __constant__ int c_hl[4]   = {56, 28, 14, 7};
__device__ __constant__ int c_offs[4] = {0, 3136, 3920, 4116};

// ---------------------------------------------------------------------------
// Scratch
// ---------------------------------------------------------------------------
__device__ float g_Q   [(size_t)NTOK * Dm];
__device__ float g_REF [(size_t)NTOK * 2];
__device__ float g_OA  [(size_t)NTOK * MOA2];   // OFF | ATT (fp32)
__device__ float g_A2  [(size_t)NTOK * Dm];
__device__ float g_X   [(size_t)NTOK * Dm];
__device__ float g_Y   [(size_t)NTOK * Dm];
__device__ float g_ball[MVOA];

// fp16 buffers (activations and hi-only weights)
__device__ __half g_Qh  [(size_t)NTOK * Dm];
__device__ __half g_Vh  [(size_t)NTOK * Dm];    // projected V, fp16
__device__ __half g_ACCh[(size_t)NTOK * Dm];
__device__ __half g_Xh  [(size_t)NTOK * Dm];
__device__ __half g_Hbh [(size_t)NTOK * DFFm];
__device__ __half g_Wah [(size_t)Dm * MVOA];
__device__ __half g_Woh [(size_t)Dm * Dm];
__device__ __half g_W1h [(size_t)Dm * DFFm];
__device__ __half g_W2h [(size_t)DFFm * Dm];

// ---------------------------------------------------------------------------
__device__ __forceinline__ int scale_of(int p, int& loc) {
    if (p < 3136)      { loc = p;        return 0; }
    else if (p < 3920) { loc = p - 3136; return 1; }
    else if (p < 4116) { loc = p - 3920; return 2; }
    else               { loc = p - 4116; return 3; }
}

// ---------------------------------------------------------------------------
// pack: srcs -> Q fp32 + Qh fp16; refs -> REF
// ---------------------------------------------------------------------------
__global__ void pack_q_kernel(const float* __restrict__ s0, const float* __restrict__ s1,
                              const float* __restrict__ s2, const float* __restrict__ s3,
                              float* __restrict__ Q, __half* __restrict__ Qh)
{
    int e = blockIdx.x * blockDim.x + threadIdx.x;
    const int total = NTOK * (Dm / 4);
    if (e >= total) return;
    int n  = e >> 7;
    int d4 = e & 127;
    int b = n / LQ;
    int p = n % LQ;
    int loc;
    int l = scale_of(p, loc);
    const float* src = (l == 0) ? s0 : (l == 1) ? s1 : (l == 2) ? s2 : s3;
    int lq = c_wl[l] * c_hl[l];
    float4 v = reinterpret_cast<const float4*>(src)[(size_t)(b * lq + loc) * 128 + d4];
    reinterpret_cast<float4*>(Q)[(size_t)n * 128 + d4] = v;

    __half h[4] = {__float2half(v.x), __float2half(v.y), __float2half(v.z), __float2half(v.w)};
    *reinterpret_cast<uint2*>(Qh + (size_t)n * Dm + d4 * 4) = *reinterpret_cast<uint2*>(h);
}

__global__ void pack_ref_kernel(const float* __restrict__ r0, const float* __restrict__ r1,
                                const float* __restrict__ r2, const float* __restrict__ r3,
                                float* __restrict__ REF)
{
    int n = blockIdx.x * blockDim.x + threadIdx.x;
    if (n >= NTOK) return;
    int b = n / LQ;
    int p = n % LQ;
    int loc;
    int l = scale_of(p, loc);
    const float* src = (l == 0) ? r0 : (l == 1) ? r1 : (l == 2) ? r2 : r3;
    int lq = c_wl[l] * c_hl[l];
    REF[(size_t)n * 2 + 0] = src[(size_t)(b * lq + loc) * 2 + 0];
    REF[(size_t)n * 2 + 1] = src[(size_t)(b * lq + loc) * 2 + 1];
}

// merge Wv/Woff/Wattn -> fp16 [512, 896] (+ merged fp32 bias)
__global__ void merge_h_kernel(const float* __restrict__ Wv, const float* __restrict__ Woff,
                               const float* __restrict__ Wattn,
                               const float* __restrict__ bv, const float* __restrict__ boff,
                               const float* __restrict__ battn,
                               __half* __restrict__ Wah, float* __restrict__ ball)
{
    int i = blockIdx.x * blockDim.x + threadIdx.x;
    if (i < Dm * MVOA) {
        int r = i / MVOA, c = i % MVOA;
        float w;
        if (c < 512)       w = Wv[r * 512 + c];
        else if (c < 768)  w = Woff[r * 256 + (c - 512)];
        else               w = Wattn[r * 128 + (c - 768)];
        Wah[i] = __float2half(w);
    }
    if (i < MVOA)
        ball[i] = (i < 512) ? bv[i] : (i < 768) ? boff[i - 512] : battn[i - 768];
}

// fp32 -> fp16 convert
__global__ void conv_w_kernel(const float* __restrict__ W, __half* __restrict__ out, int total)
{
    int i = blockIdx.x * blockDim.x + threadIdx.x;
    if (i >= total) return;
    out[i] = __float2half(W[i]);
}

// ---------------------------------------------------------------------------
// fp16 GEMM via mma.sync.m16n8k16.f32.f16.f16.f32, 4-stage cp.async pipeline.
//   C[N,M] = A[N,K] @ W[K,M] + bias
// 128x128x32 tiles, 8 warps (64x32).
// MODE 0: fp32 out. MODE 1: relu -> fp16 out.
// MODE 2: colBase<512 -> fp16 to Vh[m*512+col]; else fp32 to OA[m*384+col-512].
// ---------------------------------------------------------------------------
#define LDSM4(r, addr) \
    asm volatile("ldmatrix.sync.aligned.m8n8.x4.shared.b16 {%0,%1,%2,%3}, [%4];" \
                 : "=r"((r)[0]), "=r"((r)[1]), "=r"((r)[2]), "=r"((r)[3]) : "r"(addr))
#define LDSM4T(r, addr) \
    asm volatile("ldmatrix.sync.aligned.m8n8.x4.trans.shared.b16 {%0,%1,%2,%3}, [%4];" \
                 : "=r"((r)[0]), "=r"((r)[1]), "=r"((r)[2]), "=r"((r)[3]) : "r"(addr))
#define MMA16816H(c, a, b) \
    asm volatile("mma.sync.aligned.m16n8k16.row.col.f32.f16.f16.f32 " \
                 "{%0,%1,%2,%3}, {%4,%5,%6,%7}, {%8,%9}, {%0,%1,%2,%3};" \
                 : "+f"((c)[0]), "+f"((c)[1]), "+f"((c)[2]), "+f"((c)[3]) \
                 : "r"((a)[0]), "r"((a)[1]), "r"((a)[2]), "r"((a)[3]), \
                   "r"((b)[0]), "r"((b)[1]))

#define STAGE_BYTES 18944            // 10240 (A) + 8704 (B)
#define SMEM_GEMM   (4 * STAGE_BYTES)

template<int MODE>
__global__ __launch_bounds__(256, 2)
void gemm_fp16_kernel(const __half* __restrict__ A,
                      const __half* __restrict__ W,
                      const float* __restrict__ bias, void* __restrict__ Cout,
                      void* __restrict__ Cout2,
                      int N, int K, int M)
{
    extern __shared__ char smem[];
    const uint32_t sdata = (uint32_t)__cvta_generic_to_shared(smem);

    const int tid  = threadIdx.x;
    const int lane = tid & 31;
    const int wid  = tid >> 5;
    const int wm = (wid & 1) * 64;
    const int wn = (wid >> 1) * 32;
    const int rowBase = blockIdx.y * 128;
    const int colBase = blockIdx.x * 128;

    const int lrowA = lane & 15;
    const int lcolA = (lane >> 4) * 8;
    const uint32_t aFragOff = (uint32_t)((wm + lrowA) * 80 + lcolA * 2);
    const int grp = lane >> 3;
    const int rB  = lane & 7;
    const uint32_t bFragOff = (uint32_t)(10240 + ((grp & 1) * 8 + rB) * 272 + (grp >> 1) * 16 + wn * 2);

    const int T = K >> 5;

    float acc[4][4][4];
#pragma unroll
    for (int i = 0; i < 4; i++)
#pragma unroll
        for (int j = 0; j < 4; j++)
#pragma unroll
            for (int r = 0; r < 4; r++) acc[i][j][r] = 0.f;

    auto loadStage = [&](int t, int stage) {
        int kp0 = t << 5;
        uint32_t sb = sdata + stage * STAGE_BYTES;
#pragma unroll
        for (int i = 0; i < 2; i++) {
            int id = tid * 2 + i;
            int r = id >> 2, c = id & 3;
            int gr = rowBase + r;
            const void* src = (const void*)(A + (size_t)gr * K + kp0 + c * 8);
            uint32_t dst = sb + r * 80 + c * 16;
            int sz = (gr < N) ? 16 : 0;
            asm volatile("cp.async.cg.shared.global [%0], [%1], 16, %2;"
                         :: "r"(dst), "l"(src), "r"(sz));
        }
#pragma unroll
        for (int i = 0; i < 2; i++) {
            int id = tid * 2 + i;
            int r = id >> 4, c = id & 15;
            const void* src = (const void*)(W + (size_t)(kp0 + r) * M + colBase + c * 8);
            uint32_t dst = sb + 10240 + r * 272 + c * 16;
            asm volatile("cp.async.cg.shared.global [%0], [%1], 16;"
                         :: "r"(dst), "l"(src));
        }
        asm volatile("cp.async.commit_group;" ::: "memory");
    };

    loadStage(0, 0);
    if (T > 1) loadStage(1, 1);
    if (T > 2) loadStage(2, 2);

    for (int t = 0; t < T; t++) {
        int rem = T - 1 - t;
        if (rem >= 2)      asm volatile("cp.async.wait_group 2;" ::: "memory");
        else if (rem == 1) asm volatile("cp.async.wait_group 1;" ::: "memory");
        else               asm volatile("cp.async.wait_group 0;" ::: "memory");
        __syncthreads();

        if (t + 3 < T) loadStage(t + 3, (t + 3) & 3);

        uint32_t sb = sdata + (t & 3) * STAGE_BYTES;
        uint32_t aBase = sb + aFragOff;
        uint32_t bBase = sb + bFragOff;
#pragma unroll
        for (int ks = 0; ks < 2; ks++) {
            uint32_t af[4][4];
            uint32_t bfr[4][2];
            uint32_t aB = aBase + ks * 32;
            uint32_t bB = bBase + ks * 4352;
#pragma unroll
            for (int mt = 0; mt < 4; mt++) LDSM4(af[mt], aB + mt * 1280);
#pragma unroll
            for (int np = 0; np < 2; np++) {
                uint32_t r4[4];
                LDSM4T(r4, bB + np * 32);
                bfr[np * 2][0] = r4[0]; bfr[np * 2][1] = r4[1];
                bfr[np * 2 + 1][0] = r4[2]; bfr[np * 2 + 1][1] = r4[3];
            }
#pragma unroll
            for (int mt = 0; mt < 4; mt++)
#pragma unroll
                for (int nt = 0; nt < 4; nt++)
                    MMA16816H(acc[mt][nt], af[mt], bfr[nt]);
        }
    }

    // epilogue
    const int mr = lane >> 2;
    const int nc = (lane & 3) * 2;
    const bool vpart = (MODE == 2) && (colBase < 512);

#pragma unroll
    for (int mt = 0; mt < 4; mt++) {
#pragma unroll
        for (int nt = 0; nt < 4; nt++) {
            int n0 = colBase + wn + nt * 8 + nc;
            float bb0 = bias[n0], bb1 = bias[n0 + 1];
#pragma unroll
            for (int half = 0; half < 2; half++) {
                int m = rowBase + wm + mt * 16 + mr + half * 8;
                if (m >= N) continue;
                float v0 = acc[mt][nt][half * 2 + 0] + bb0;
                float v1 = acc[mt][nt][half * 2 + 1] + bb1;
                if (MODE == 0) {
                    *reinterpret_cast<float2*>((float*)Cout + (size_t)m * M + n0) = make_float2(v0, v1);
                } else if (MODE == 1) {
                    v0 = fmaxf(v0, 0.f); v1 = fmaxf(v1, 0.f);
                    __half2 hv; hv.x = __float2half(v0); hv.y = __float2half(v1);
                    *reinterpret_cast<__half2*>((__half*)Cout + (size_t)m * M + n0) = hv;
                } else {
                    if (vpart) {
                        __half2 hv; hv.x = __float2half(v0); hv.y = __float2half(v1);
                        *reinterpret_cast<__half2*>((__half*)Cout + (size_t)m * Dm + n0) = hv;
                    } else {
                        *reinterpret_cast<float2*>((float*)Cout2 + (size_t)m * MOA2 + (n0 - 512)) = make_float2(v0, v1);
                    }
                }
            }
        }
    }
}

// ---------------------------------------------------------------------------
// softmax over groups of 16 (ATT at OA col 256)
// ---------------------------------------------------------------------------
__global__ void softmax16_kernel(float* __restrict__ OA)
{
    int r = blockIdx.x * blockDim.x + threadIdx.x;
    if (r >= NTOK * Hh) return;
    int n = r >> 3, h = r & 7;
    float* p = OA + (size_t)n * MOA2 + 256 + h * 16;
    float v[16], mx = -1e30f;
#pragma unroll
    for (int i = 0; i < 16; i++) { v[i] = p[i]; mx = fmaxf(mx, v[i]); }
    float s = 0.f;
#pragma unroll
    for (int i = 0; i < 16; i++) { v[i] = expf(v[i] - mx); s += v[i]; }
    float inv = 1.f / s;
#pragma unroll
    for (int i = 0; i < 16; i++) p[i] = v[i] * inv;
}

// ---------------------------------------------------------------------------
// Deformable sampling; V fp16 [N,512]. Lane handles d = 2*lane, 2*lane+1.
// ---------------------------------------------------------------------------
__global__ void sample_kernel(const __half* __restrict__ Vh, const float* __restrict__ OA,
                              const float* __restrict__ REF, __half* __restrict__ ACCh)
{
    int wid = blockIdx.x * (blockDim.x / 32) + (threadIdx.x / 32);
    if (wid >= NTOK * Hh) return;
    int lane = threadIdx.x & 31;
    int n = wid / Hh;
    int h = wid % Hh;
    int b = n / LQ;

    float refx = REF[(size_t)n * 2 + 0];
    float refy = REF[(size_t)n * 2 + 1];
    const float* offp = OA + (size_t)n * MOA2;
    const float* attp = OA + (size_t)n * MOA2 + 256;

    float acc0 = 0.f, acc1 = 0.f;

#pragma unroll
    for (int s = 0; s < Ss; s++) {
        int wl = c_wl[s], hl = c_hl[s];
        int base_tok = b * LQ + c_offs[s];
        float fwl = (float)wl, fhl = (float)hl;
#pragma unroll
        for (int k = 0; k < Kk; k++) {
            float w  = attp[h * 16 + s * 4 + k];
            float ox = offp[(((h * 4 + s) * 4 + k) * 2) + 0];
            float oy = offp[(((h * 4 + s) * 4 + k) * 2) + 1];
            float x = refx * fwl + ox - 0.5f;
            float y = refy * fhl + oy - 0.5f;
            float x0f = floorf(x), y0f = floorf(y);
            int x0 = (int)x0f, y0 = (int)y0f;
            float wx1 = x - x0f, wx0 = 1.f - wx1;
            float wy1 = y - y0f, wy0 = 1.f - wy1;
#pragma unroll
            for (int c = 0; c < 4; c++) {
                int xi = x0 + (c & 1);
                int yi = y0 + (c >> 1);
                float wc = ((c & 1) ? wx1 : wx0) * ((c >> 1) ? wy1 : wy0);
                bool valid = (xi >= 0) && (xi < wl) && (yi >= 0) && (yi < hl);
                if (valid) {
                    int idx = yi * wl + xi;
                    const __half2* vp = reinterpret_cast<const __half2*>(
                        Vh + ((size_t)(base_tok + idx) * Dm + h * DHh));
                    float ww = w * wc;
                    __half2 hv = __ldg(vp + lane);
                    float2 fv = __half22float2(hv);
                    acc0 = fmaf(ww, fv.x, acc0);
                    acc1 = fmaf(ww, fv.y, acc1);
                }
            }
        }
    }
    size_t base = (size_t)n * Dm + h * DHh;
    __half2 hv; hv.x = __float2half(acc0); hv.y = __float2half(acc1);
    *reinterpret_cast<__half2*>(ACCh + base + 2 * lane) = hv;
}

// ---------------------------------------------------------------------------
// Fused residual-add + LayerNorm; optionally emits fp16 copy.
// ---------------------------------------------------------------------------
__global__ void add_layernorm_kernel(const float* __restrict__ A, const float* __restrict__ Bv,
                                     const float* __restrict__ g, const float* __restrict__ be,
                                     float* __restrict__ out, __half* __restrict__ outh)
{
    int n = blockIdx.x;
    int t = threadIdx.x;
    float v[4];
    float s = 0.f, ss = 0.f;
#pragma unroll
    for (int i = 0; i < 4; i++) {
        int d = t + i * 128;
        float x = A[(size_t)n * Dm + d] + Bv[(size_t)n * Dm + d];
        v[i] = x; s += x; ss += x * x;
    }
#pragma unroll
    for (int o = 16; o > 0; o >>= 1) {
        s  += __shfl_xor_sync(0xffffffffu, s,  o);
        ss += __shfl_xor_sync(0xffffffffu, ss, o);
    }
    __shared__ float sh[8];
    int w = t >> 5, ln = t & 31;
    if (ln == 0) { sh[w] = s; sh[4 + w] = ss; }
    __syncthreads();
    float ts  = sh[0] + sh[1] + sh[2] + sh[3];
    float tss = sh[4] + sh[5] + sh[6] + sh[7];
    float mu  = ts * (1.f / Dm);
    float var = tss * (1.f / Dm) - mu * mu;
    float inv = rsqrtf(var + 1e-5f);
#pragma unroll
    for (int i = 0; i < 4; i++) {
        int d = t + i * 128;
        float o = (v[i] - mu) * inv * g[d] + be[d];
        out[(size_t)n * Dm + d] = o;
        if (outh) outh[(size_t)n * Dm + d] = __float2half(o);
    }
}

// ---------------------------------------------------------------------------
// Launch
// ---------------------------------------------------------------------------
extern "C" void kernel_launch(void* const* d_in, const int* in_sizes, int n_in,
                              void* d_out, int out_size)
{
    const float* srcs[4] = {nullptr, nullptr, nullptr, nullptr};
    const float* refs[4] = {nullptr, nullptr, nullptr, nullptr};
    const int src_sz[4] = {Bb * 56 * 56 * Dm, Bb * 28 * 28 * Dm, Bb * 14 * 14 * Dm, Bb * 7 * 7 * Dm};
    const int ref_sz[4] = {Bb * 56 * 56 * 2,  Bb * 28 * 28 * 2,  Bb * 14 * 14 * 2,  Bb * 7 * 7 * 2};
    for (int i = 0; i < 8; i++) {
        int sz = in_sizes[i];
        for (int l = 0; l < 4; l++) {
            if (sz == src_sz[l] && !srcs[l]) { srcs[l] = (const float*)d_in[i]; goto next; }
        }
        for (int l = 0; l < 4; l++) {
            if (sz == ref_sz[l] && !refs[l]) { refs[l] = (const float*)d_in[i]; goto next; }
        }
    next:;
    }

    const float* Wv    = (const float*)d_in[8];
    const float* bv    = (const float*)d_in[9];
    const float* Woff  = (const float*)d_in[10];
    const float* boff  = (const float*)d_in[11];
    const float* Wattn = (const float*)d_in[12];
    const float* battn = (const float*)d_in[13];
    const float* Wo    = (const float*)d_in[14];
    const float* bo    = (const float*)d_in[15];
    const float* W1    = (const float*)d_in[16];
    const float* b1    = (const float*)d_in[17];
    const float* W2    = (const float*)d_in[18];
    const float* b2    = (const float*)d_in[19];
    const float* g1    = (const float*)d_in[20];
    const float* be1   = (const float*)d_in[21];
    const float* g2    = (const float*)d_in[22];
    const float* be2   = (const float*)d_in[23];
    float* out = (float*)d_out;

    float *Q, *REF, *OA, *A2, *X, *Y, *ball;
    __half *Qh, *Vh, *ACCh, *Xh, *Hbh, *Wah, *Woh, *W1h, *W2h;
    cudaGetSymbolAddress((void**)&Q,    g_Q);
    cudaGetSymbolAddress((void**)&REF,  g_REF);
    cudaGetSymbolAddress((void**)&OA,   g_OA);
    cudaGetSymbolAddress((void**)&A2,   g_A2);
    cudaGetSymbolAddress((void**)&X,    g_X);
    cudaGetSymbolAddress((void**)&Y,    g_Y);
    cudaGetSymbolAddress((void**)&ball, g_ball);
    cudaGetSymbolAddress((void**)&Qh,   g_Qh);
    cudaGetSymbolAddress((void**)&Vh,   g_Vh);
    cudaGetSymbolAddress((void**)&ACCh, g_ACCh);
    cudaGetSymbolAddress((void**)&Xh,   g_Xh);
    cudaGetSymbolAddress((void**)&Hbh,  g_Hbh);
    cudaGetSymbolAddress((void**)&Wah,  g_Wah);
    cudaGetSymbolAddress((void**)&Woh,  g_Woh);
    cudaGetSymbolAddress((void**)&W1h,  g_W1h);
    cudaGetSymbolAddress((void**)&W2h,  g_W2h);

    cudaFuncSetAttribute(gemm_fp16_kernel<0>, cudaFuncAttributeMaxDynamicSharedMemorySize, SMEM_GEMM);
    cudaFuncSetAttribute(gemm_fp16_kernel<1>, cudaFuncAttributeMaxDynamicSharedMemorySize, SMEM_GEMM);
    cudaFuncSetAttribute(gemm_fp16_kernel<2>, cudaFuncAttributeMaxDynamicSharedMemorySize, SMEM_GEMM);

    // 1. pack + weight prep
    {
        int total = NTOK * (Dm / 4);
        pack_q_kernel<<<(total + 255) / 256, 256>>>(srcs[0], srcs[1], srcs[2], srcs[3], Q, Qh);
        pack_ref_kernel<<<(NTOK + 255) / 256, 256>>>(refs[0], refs[1], refs[2], refs[3], REF);
        merge_h_kernel<<<(Dm * MVOA + 255) / 256, 256>>>(Wv, Woff, Wattn, bv, boff, battn, Wah, ball);
        conv_w_kernel<<<(Dm * Dm + 255) / 256, 256>>>(Wo, Woh, Dm * Dm);
        conv_w_kernel<<<(Dm * DFFm + 255) / 256, 256>>>(W1, W1h, Dm * DFFm);
        conv_w_kernel<<<(DFFm * Dm + 255) / 256, 256>>>(W2, W2h, DFFm * Dm);
    }

    const int rowBlocks = (NTOK + 127) / 128;   // 131
    dim3 blk(256);

    // 2. [Vh | OA] = Q @ [Wv|Woff|Wattn] + bias
    gemm_fp16_kernel<2><<<dim3(MVOA / 128, rowBlocks), blk, SMEM_GEMM>>>(Qh, Wah, ball, Vh, OA, NTOK, Dm, MVOA);
    // 3. softmax
    softmax16_kernel<<<(NTOK * Hh + 255) / 256, 256>>>(OA);
    // 4. sampling -> ACCh
    {
        int warps = NTOK * Hh;
        sample_kernel<<<(warps + 7) / 8, 256>>>(Vh, OA, REF, ACCh);
    }
    // 5. A2 = ACC @ Wo + bo
    gemm_fp16_kernel<0><<<dim3(Dm / 128, rowBlocks), blk, SMEM_GEMM>>>(ACCh, Woh, bo, A2, nullptr, NTOK, Dm, Dm);
    // 6. X = LN(Q + A2)  (+ Xh)
    add_layernorm_kernel<<<NTOK, 128>>>(Q, A2, g1, be1, X, Xh);
    // 7. Hbh = fp16(relu(X @ W1 + b1))
    gemm_fp16_kernel<1><<<dim3(DFFm / 128, rowBlocks), blk, SMEM_GEMM>>>(Xh, W1h, b1, Hbh, nullptr, NTOK, Dm, DFFm);
    // 8. Y = Hb @ W2 + b2
    gemm_fp16_kernel<0><<<dim3(Dm / 128, rowBlocks), blk, SMEM_GEMM>>>(Hbh, W2h, b2, Y, nullptr, NTOK, DFFm, Dm);
    // 9. out = LN(X + Y)
    add_layernorm_kernel<<<NTOK, 128>>>(X, Y, g2, be2, out, nullptr);
}

// round 10
// speedup vs baseline: 4.4215x; 1.0035x over previous
#include <cuda_runtime.h>
#include <cuda_fp16.h>
#include <cstdint>

// ---------------------------------------------------------------------------
// Problem constants
// ---------------------------------------------------------------------------
#define Dm    512
#define Hh    8
#define DHh   64
#define DFFm  2048
#define Kk    4
#define Ss    4
#define Bb    4
#define LQ    4165
#define NTOK  (Bb * LQ)     // 16660
#define MVOA  896           // merged V(512) + OFF(256) + ATT(128)
#define MOA2  384           // OFF+ATT width

__device__ __constant__ int c_wl[4]   = {56, 28, 14, 7};
__device__ __constant__ int c_hl[4]   = {56, 28, 14, 7};
__device__ __constant__ int c_offs[4] = {0, 3136, 3920, 4116};

// ---------------------------------------------------------------------------
// Scratch
// ---------------------------------------------------------------------------
__device__ float g_REF [(size_t)NTOK * 2];
__device__ float g_OA  [(size_t)NTOK * MOA2];   // OFF | ATT logits (fp32)
__device__ float g_ball[MVOA];

// fp16 buffers
__device__ __half g_Qh  [(size_t)NTOK * Dm];
__device__ __half g_Vh  [(size_t)NTOK * Dm];
__device__ __half g_ACCh[(size_t)NTOK * Dm];
__device__ __half g_A2h [(size_t)NTOK * Dm];
__device__ __half g_Xh  [(size_t)NTOK * Dm];
__device__ __half g_Hbh [(size_t)NTOK * DFFm];
__device__ __half g_Yh  [(size_t)NTOK * Dm];
__device__ __half g_Wah [(size_t)Dm * MVOA];
__device__ __half g_Woh [(size_t)Dm * Dm];
__device__ __half g_W1h [(size_t)Dm * DFFm];
__device__ __half g_W2h [(size_t)DFFm * Dm];

// ---------------------------------------------------------------------------
__device__ __forceinline__ int scale_of(int p, int& loc) {
    if (p < 3136)      { loc = p;        return 0; }
    else if (p < 3920) { loc = p - 3136; return 1; }
    else if (p < 4116) { loc = p - 3920; return 2; }
    else               { loc = p - 4116; return 3; }
}

// ---------------------------------------------------------------------------
// pack: srcs -> Qh fp16; refs -> REF
// ---------------------------------------------------------------------------
__global__ void pack_q_kernel(const float* __restrict__ s0, const float* __restrict__ s1,
                              const float* __restrict__ s2, const float* __restrict__ s3,
                              __half* __restrict__ Qh)
{
    int e = blockIdx.x * blockDim.x + threadIdx.x;
    const int total = NTOK * (Dm / 4);
    if (e >= total) return;
    int n  = e >> 7;
    int d4 = e & 127;
    int b = n / LQ;
    int p = n % LQ;
    int loc;
    int l = scale_of(p, loc);
    const float* src = (l == 0) ? s0 : (l == 1) ? s1 : (l == 2) ? s2 : s3;
    int lq = c_wl[l] * c_hl[l];
    float4 v = reinterpret_cast<const float4*>(src)[(size_t)(b * lq + loc) * 128 + d4];
    __half h[4] = {__float2half(v.x), __float2half(v.y), __float2half(v.z), __float2half(v.w)};
    *reinterpret_cast<uint2*>(Qh + (size_t)n * Dm + d4 * 4) = *reinterpret_cast<uint2*>(h);
}

__global__ void pack_ref_kernel(const float* __restrict__ r0, const float* __restrict__ r1,
                                const float* __restrict__ r2, const float* __restrict__ r3,
                                float* __restrict__ REF)
{
    int n = blockIdx.x * blockDim.x + threadIdx.x;
    if (n >= NTOK) return;
    int b = n / LQ;
    int p = n % LQ;
    int loc;
    int l = scale_of(p, loc);
    const float* src = (l == 0) ? r0 : (l == 1) ? r1 : (l == 2) ? r2 : r3;
    int lq = c_wl[l] * c_hl[l];
    REF[(size_t)n * 2 + 0] = src[(size_t)(b * lq + loc) * 2 + 0];
    REF[(size_t)n * 2 + 1] = src[(size_t)(b * lq + loc) * 2 + 1];
}

// merge Wv/Woff/Wattn -> fp16 [512, 896] (+ merged fp32 bias)
__global__ void merge_h_kernel(const float* __restrict__ Wv, const float* __restrict__ Woff,
                               const float* __restrict__ Wattn,
                               const float* __restrict__ bv, const float* __restrict__ boff,
                               const float* __restrict__ battn,
                               __half* __restrict__ Wah, float* __restrict__ ball)
{
    int i = blockIdx.x * blockDim.x + threadIdx.x;
    if (i < Dm * MVOA) {
        int r = i / MVOA, c = i % MVOA;
        float w;
        if (c < 512)       w = Wv[r * 512 + c];
        else if (c < 768)  w = Woff[r * 256 + (c - 512)];
        else               w = Wattn[r * 128 + (c - 768)];
        Wah[i] = __float2half(w);
    }
    if (i < MVOA)
        ball[i] = (i < 512) ? bv[i] : (i < 768) ? boff[i - 512] : battn[i - 768];
}

// fp32 -> fp16 convert
__global__ void conv_w_kernel(const float* __restrict__ W, __half* __restrict__ out, int total)
{
    int i = blockIdx.x * blockDim.x + threadIdx.x;
    if (i >= total) return;
    out[i] = __float2half(W[i]);
}

// ---------------------------------------------------------------------------
// fp16 GEMM via mma.sync.m16n8k16.f32.f16.f16.f32, 4-stage cp.async pipeline.
//   C[N,M] = A[N,K] @ W[K,M] + bias
// 128x128x32 tiles, 8 warps (64x32).
// MODE 0: fp32 out. MODE 1: relu -> fp16. MODE 3: fp16 (no relu).
// MODE 2: colBase<512 -> fp16 to Vh[m*512+col]; else fp32 to OA[m*384+col-512].
// ---------------------------------------------------------------------------
#define LDSM4(r, addr) \
    asm volatile("ldmatrix.sync.aligned.m8n8.x4.shared.b16 {%0,%1,%2,%3}, [%4];" \
                 : "=r"((r)[0]), "=r"((r)[1]), "=r"((r)[2]), "=r"((r)[3]) : "r"(addr))
#define LDSM4T(r, addr) \
    asm volatile("ldmatrix.sync.aligned.m8n8.x4.trans.shared.b16 {%0,%1,%2,%3}, [%4];" \
                 : "=r"((r)[0]), "=r"((r)[1]), "=r"((r)[2]), "=r"((r)[3]) : "r"(addr))
#define MMA16816H(c, a, b) \
    asm volatile("mma.sync.aligned.m16n8k16.row.col.f32.f16.f16.f32 " \
                 "{%0,%1,%2,%3}, {%4,%5,%6,%7}, {%8,%9}, {%0,%1,%2,%3};" \
                 : "+f"((c)[0]), "+f"((c)[1]), "+f"((c)[2]), "+f"((c)[3]) \
                 : "r"((a)[0]), "r"((a)[1]), "r"((a)[2]), "r"((a)[3]), \
                   "r"((b)[0]), "r"((b)[1]))

#define STAGE_BYTES 18944            // 10240 (A) + 8704 (B)
#define SMEM_GEMM   (4 * STAGE_BYTES)

template<int MODE>
__global__ __launch_bounds__(256, 2)
void gemm_fp16_kernel(const __half* __restrict__ A,
                      const __half* __restrict__ W,
                      const float* __restrict__ bias, void* __restrict__ Cout,
                      void* __restrict__ Cout2,
                      int N, int K, int M)
{
    extern __shared__ char smem[];
    const uint32_t sdata = (uint32_t)__cvta_generic_to_shared(smem);

    const int tid  = threadIdx.x;
    const int lane = tid & 31;
    const int wid  = tid >> 5;
    const int wm = (wid & 1) * 64;
    const int wn = (wid >> 1) * 32;
    const int rowBase = blockIdx.y * 128;
    const int colBase = blockIdx.x * 128;

    const int lrowA = lane & 15;
    const int lcolA = (lane >> 4) * 8;
    const uint32_t aFragOff = (uint32_t)((wm + lrowA) * 80 + lcolA * 2);
    const int grp = lane >> 3;
    const int rB  = lane & 7;
    const uint32_t bFragOff = (uint32_t)(10240 + ((grp & 1) * 8 + rB) * 272 + (grp >> 1) * 16 + wn * 2);

    const int T = K >> 5;

    float acc[4][4][4];
#pragma unroll
    for (int i = 0; i < 4; i++)
#pragma unroll
        for (int j = 0; j < 4; j++)
#pragma unroll
            for (int r = 0; r < 4; r++) acc[i][j][r] = 0.f;

    auto loadStage = [&](int t, int stage) {
        int kp0 = t << 5;
        uint32_t sb = sdata + stage * STAGE_BYTES;
#pragma unroll
        for (int i = 0; i < 2; i++) {
            int id = tid * 2 + i;
            int r = id >> 2, c = id & 3;
            int gr = rowBase + r;
            const void* src = (const void*)(A + (size_t)gr * K + kp0 + c * 8);
            uint32_t dst = sb + r * 80 + c * 16;
            int sz = (gr < N) ? 16 : 0;
            asm volatile("cp.async.cg.shared.global [%0], [%1], 16, %2;"
                         :: "r"(dst), "l"(src), "r"(sz));
        }
#pragma unroll
        for (int i = 0; i < 2; i++) {
            int id = tid * 2 + i;
            int r = id >> 4, c = id & 15;
            const void* src = (const void*)(W + (size_t)(kp0 + r) * M + colBase + c * 8);
            uint32_t dst = sb + 10240 + r * 272 + c * 16;
            asm volatile("cp.async.cg.shared.global [%0], [%1], 16;"
                         :: "r"(dst), "l"(src));
        }
        asm volatile("cp.async.commit_group;" ::: "memory");
    };

    loadStage(0, 0);
    if (T > 1) loadStage(1, 1);
    if (T > 2) loadStage(2, 2);

    for (int t = 0; t < T; t++) {
        int rem = T - 1 - t;
        if (rem >= 2)      asm volatile("cp.async.wait_group 2;" ::: "memory");
        else if (rem == 1) asm volatile("cp.async.wait_group 1;" ::: "memory");
        else               asm volatile("cp.async.wait_group 0;" ::: "memory");
        __syncthreads();

        if (t + 3 < T) loadStage(t + 3, (t + 3) & 3);

        uint32_t sb = sdata + (t & 3) * STAGE_BYTES;
        uint32_t aBase = sb + aFragOff;
        uint32_t bBase = sb + bFragOff;
#pragma unroll
        for (int ks = 0; ks < 2; ks++) {
            uint32_t af[4][4];
            uint32_t bfr[4][2];
            uint32_t aB = aBase + ks * 32;
            uint32_t bB = bBase + ks * 4352;
#pragma unroll
            for (int mt = 0; mt < 4; mt++) LDSM4(af[mt], aB + mt * 1280);
#pragma unroll
            for (int np = 0; np < 2; np++) {
                uint32_t r4[4];
                LDSM4T(r4, bB + np * 32);
                bfr[np * 2][0] = r4[0]; bfr[np * 2][1] = r4[1];
                bfr[np * 2 + 1][0] = r4[2]; bfr[np * 2 + 1][1] = r4[3];
            }
#pragma unroll
            for (int mt = 0; mt < 4; mt++)
#pragma unroll
                for (int nt = 0; nt < 4; nt++)
                    MMA16816H(acc[mt][nt], af[mt], bfr[nt]);
        }
    }

    // epilogue
    const int mr = lane >> 2;
    const int nc = (lane & 3) * 2;
    const bool vpart = (MODE == 2) && (colBase < 512);

#pragma unroll
    for (int mt = 0; mt < 4; mt++) {
#pragma unroll
        for (int nt = 0; nt < 4; nt++) {
            int n0 = colBase + wn + nt * 8 + nc;
            float bb0 = bias[n0], bb1 = bias[n0 + 1];
#pragma unroll
            for (int half = 0; half < 2; half++) {
                int m = rowBase + wm + mt * 16 + mr + half * 8;
                if (m >= N) continue;
                float v0 = acc[mt][nt][half * 2 + 0] + bb0;
                float v1 = acc[mt][nt][half * 2 + 1] + bb1;
                if (MODE == 0) {
                    *reinterpret_cast<float2*>((float*)Cout + (size_t)m * M + n0) = make_float2(v0, v1);
                } else if (MODE == 1 || MODE == 3) {
                    if (MODE == 1) { v0 = fmaxf(v0, 0.f); v1 = fmaxf(v1, 0.f); }
                    __half2 hv; hv.x = __float2half(v0); hv.y = __float2half(v1);
                    *reinterpret_cast<__half2*>((__half*)Cout + (size_t)m * M + n0) = hv;
                } else {
                    if (vpart) {
                        __half2 hv; hv.x = __float2half(v0); hv.y = __float2half(v1);
                        *reinterpret_cast<__half2*>((__half*)Cout + (size_t)m * Dm + n0) = hv;
                    } else {
                        *reinterpret_cast<float2*>((float*)Cout2 + (size_t)m * MOA2 + (n0 - 512)) = make_float2(v0, v1);
                    }
                }
            }
        }
    }
}

// ---------------------------------------------------------------------------
// Deformable sampling with FUSED softmax. V fp16 [N,512].
// One warp per (token, head); lane handles d = 2*lane, 2*lane+1.
// ---------------------------------------------------------------------------
__global__ void sample_kernel(const __half* __restrict__ Vh, const float* __restrict__ OA,
                              const float* __restrict__ REF, __half* __restrict__ ACCh)
{
    int wid = blockIdx.x * (blockDim.x / 32) + (threadIdx.x / 32);
    if (wid >= NTOK * Hh) return;
    int lane = threadIdx.x & 31;
    int n = wid / Hh;
    int h = wid % Hh;
    int b = n / LQ;

    float refx = REF[(size_t)n * 2 + 0];
    float refy = REF[(size_t)n * 2 + 1];
    const float* offp = OA + (size_t)n * MOA2;
    const float* attp = OA + (size_t)n * MOA2 + 256 + h * 16;

    // fused softmax over 16 logits (computed redundantly per lane; broadcast loads)
    float lg[16], mx = -1e30f;
#pragma unroll
    for (int i = 0; i < 16; i += 4) {
        float4 l4 = *reinterpret_cast<const float4*>(attp + i);
        lg[i] = l4.x; lg[i + 1] = l4.y; lg[i + 2] = l4.z; lg[i + 3] = l4.w;
    }
#pragma unroll
    for (int i = 0; i < 16; i++) mx = fmaxf(mx, lg[i]);
    float ssum = 0.f;
#pragma unroll
    for (int i = 0; i < 16; i++) { lg[i] = expf(lg[i] - mx); ssum += lg[i]; }
    float sinv = 1.f / ssum;

    float acc0 = 0.f, acc1 = 0.f;

#pragma unroll
    for (int s = 0; s < Ss; s++) {
        int wl = c_wl[s], hl = c_hl[s];
        int base_tok = b * LQ + c_offs[s];
        float fwl = (float)wl, fhl = (float)hl;
#pragma unroll
        for (int k = 0; k < Kk; k++) {
            float w  = lg[s * 4 + k] * sinv;
            float ox = offp[(((h * 4 + s) * 4 + k) * 2) + 0];
            float oy = offp[(((h * 4 + s) * 4 + k) * 2) + 1];
            float x = refx * fwl + ox - 0.5f;
            float y = refy * fhl + oy - 0.5f;
            float x0f = floorf(x), y0f = floorf(y);
            int x0 = (int)x0f, y0 = (int)y0f;
            float wx1 = x - x0f, wx0 = 1.f - wx1;
            float wy1 = y - y0f, wy0 = 1.f - wy1;
#pragma unroll
            for (int c = 0; c < 4; c++) {
                int xi = x0 + (c & 1);
                int yi = y0 + (c >> 1);
                float wc = ((c & 1) ? wx1 : wx0) * ((c >> 1) ? wy1 : wy0);
                bool valid = (xi >= 0) && (xi < wl) && (yi >= 0) && (yi < hl);
                if (valid) {
                    int idx = yi * wl + xi;
                    const __half2* vp = reinterpret_cast<const __half2*>(
                        Vh + ((size_t)(base_tok + idx) * Dm + h * DHh));
                    float ww = w * wc;
                    __half2 hv = __ldg(vp + lane);
                    float2 fv = __half22float2(hv);
                    acc0 = fmaf(ww, fv.x, acc0);
                    acc1 = fmaf(ww, fv.y, acc1);
                }
            }
        }
    }
    size_t base = (size_t)n * Dm + h * DHh;
    __half2 hv; hv.x = __float2half(acc0); hv.y = __float2half(acc1);
    *reinterpret_cast<__half2*>(ACCh + base + 2 * lane) = hv;
}

// ---------------------------------------------------------------------------
// Fused residual-add + LayerNorm, fp16 inputs.
// Writes fp16 out (if outh) and/or fp32 out (if outf).
// ---------------------------------------------------------------------------
__global__ void add_layernorm_h_kernel(const __half* __restrict__ A, const __half* __restrict__ Bv,
                                       const float* __restrict__ g, const float* __restrict__ be,
                                       __half* __restrict__ outh, float* __restrict__ outf)
{
    int n = blockIdx.x;
    int t = threadIdx.x;   // 0..127; handles half2 idx t, t+128 (dims 2t..2t+1, 2t+256..)
    float v[4];
    float s = 0.f, ss = 0.f;
    const __half2* a2 = reinterpret_cast<const __half2*>(A + (size_t)n * Dm);
    const __half2* b2 = reinterpret_cast<const __half2*>(Bv + (size_t)n * Dm);
#pragma unroll
    for (int i = 0; i < 2; i++) {
        int d2 = t + i * 128;
        float2 fa = __half22float2(a2[d2]);
        float2 fb = __half22float2(b2[d2]);
        float x0 = fa.x + fb.x, x1 = fa.y + fb.y;
        v[i * 2] = x0; v[i * 2 + 1] = x1;
        s += x0 + x1; ss += x0 * x0 + x1 * x1;
    }
#pragma unroll
    for (int o = 16; o > 0; o >>= 1) {
        s  += __shfl_xor_sync(0xffffffffu, s,  o);
        ss += __shfl_xor_sync(0xffffffffu, ss, o);
    }
    __shared__ float sh[8];
    int w = t >> 5, ln = t & 31;
    if (ln == 0) { sh[w] = s; sh[4 + w] = ss; }
    __syncthreads();
    float ts  = sh[0] + sh[1] + sh[2] + sh[3];
    float tss = sh[4] + sh[5] + sh[6] + sh[7];
    float mu  = ts * (1.f / Dm);
    float var = tss * (1.f / Dm) - mu * mu;
    float inv = rsqrtf(var + 1e-5f);
#pragma unroll
    for (int i = 0; i < 2; i++) {
        int d2 = t + i * 128;
        int d = d2 * 2;
        float o0 = (v[i * 2]     - mu) * inv * g[d]     + be[d];
        float o1 = (v[i * 2 + 1] - mu) * inv * g[d + 1] + be[d + 1];
        if (outh) {
            __half2 hv; hv.x = __float2half(o0); hv.y = __float2half(o1);
            *reinterpret_cast<__half2*>(outh + (size_t)n * Dm + d) = hv;
        }
        if (outf) {
            *reinterpret_cast<float2*>(outf + (size_t)n * Dm + d) = make_float2(o0, o1);
        }
    }
}

// ---------------------------------------------------------------------------
// Launch
// ---------------------------------------------------------------------------
extern "C" void kernel_launch(void* const* d_in, const int* in_sizes, int n_in,
                              void* d_out, int out_size)
{
    const float* srcs[4] = {nullptr, nullptr, nullptr, nullptr};
    const float* refs[4] = {nullptr, nullptr, nullptr, nullptr};
    const int src_sz[4] = {Bb * 56 * 56 * Dm, Bb * 28 * 28 * Dm, Bb * 14 * 14 * Dm, Bb * 7 * 7 * Dm};
    const int ref_sz[4] = {Bb * 56 * 56 * 2,  Bb * 28 * 28 * 2,  Bb * 14 * 14 * 2,  Bb * 7 * 7 * 2};
    for (int i = 0; i < 8; i++) {
        int sz = in_sizes[i];
        for (int l = 0; l < 4; l++) {
            if (sz == src_sz[l] && !srcs[l]) { srcs[l] = (const float*)d_in[i]; goto next; }
        }
        for (int l = 0; l < 4; l++) {
            if (sz == ref_sz[l] && !refs[l]) { refs[l] = (const float*)d_in[i]; goto next; }
        }
    next:;
    }

    const float* Wv    = (const float*)d_in[8];
    const float* bv    = (const float*)d_in[9];
    const float* Woff  = (const float*)d_in[10];
    const float* boff  = (const float*)d_in[11];
    const float* Wattn = (const float*)d_in[12];
    const float* battn = (const float*)d_in[13];
    const float* Wo    = (const float*)d_in[14];
    const float* bo    = (const float*)d_in[15];
    const float* W1    = (const float*)d_in[16];
    const float* b1    = (const float*)d_in[17];
    const float* W2    = (const float*)d_in[18];
    const float* b2    = (const float*)d_in[19];
    const float* g1    = (const float*)d_in[20];
    const float* be1   = (const float*)d_in[21];
    const float* g2    = (const float*)d_in[22];
    const float* be2   = (const float*)d_in[23];
    float* out = (float*)d_out;

    float *REF, *OA, *ball;
    __half *Qh, *Vh, *ACCh, *A2h, *Xh, *Hbh, *Yh, *Wah, *Woh, *W1h, *W2h;
    cudaGetSymbolAddress((void**)&REF,  g_REF);
    cudaGetSymbolAddress((void**)&OA,   g_OA);
    cudaGetSymbolAddress((void**)&ball, g_ball);
    cudaGetSymbolAddress((void**)&Qh,   g_Qh);
    cudaGetSymbolAddress((void**)&Vh,   g_Vh);
    cudaGetSymbolAddress((void**)&ACCh, g_ACCh);
    cudaGetSymbolAddress((void**)&A2h,  g_A2h);
    cudaGetSymbolAddress((void**)&Xh,   g_Xh);
    cudaGetSymbolAddress((void**)&Hbh,  g_Hbh);
    cudaGetSymbolAddress((void**)&Yh,   g_Yh);
    cudaGetSymbolAddress((void**)&Wah,  g_Wah);
    cudaGetSymbolAddress((void**)&Woh,  g_Woh);
    cudaGetSymbolAddress((void**)&W1h,  g_W1h);
    cudaGetSymbolAddress((void**)&W2h,  g_W2h);

    cudaFuncSetAttribute(gemm_fp16_kernel<0>, cudaFuncAttributeMaxDynamicSharedMemorySize, SMEM_GEMM);
    cudaFuncSetAttribute(gemm_fp16_kernel<1>, cudaFuncAttributeMaxDynamicSharedMemorySize, SMEM_GEMM);
    cudaFuncSetAttribute(gemm_fp16_kernel<2>, cudaFuncAttributeMaxDynamicSharedMemorySize, SMEM_GEMM);
    cudaFuncSetAttribute(gemm_fp16_kernel<3>, cudaFuncAttributeMaxDynamicSharedMemorySize, SMEM_GEMM);

    const int rowBlocks = (NTOK + 127) / 128;   // 131
    dim3 blk(256);

    // Launch order chosen so ncu (-s 5 -c 1) profiles the VOA GEMM (index 5).
    // 0,1: FFN weight converts
    conv_w_kernel<<<(Dm * DFFm + 255) / 256, 256>>>(W1, W1h, Dm * DFFm);
    conv_w_kernel<<<(DFFm * Dm + 255) / 256, 256>>>(W2, W2h, DFFm * Dm);
    // 2: merged VOA weight
    merge_h_kernel<<<(Dm * MVOA + 255) / 256, 256>>>(Wv, Woff, Wattn, bv, boff, battn, Wah, ball);
    // 3,4: packs
    pack_ref_kernel<<<(NTOK + 255) / 256, 256>>>(refs[0], refs[1], refs[2], refs[3], REF);
    {
        int total = NTOK * (Dm / 4);
        pack_q_kernel<<<(total + 255) / 256, 256>>>(srcs[0], srcs[1], srcs[2], srcs[3], Qh);
    }
    // 5: [Vh | OA] = Q @ [Wv|Woff|Wattn] + bias     <-- profiled by ncu
    gemm_fp16_kernel<2><<<dim3(MVOA / 128, rowBlocks), blk, SMEM_GEMM>>>(Qh, Wah, ball, Vh, OA, NTOK, Dm, MVOA);
    // 6: sampling (fused softmax) -> ACCh
    {
        int warps = NTOK * Hh;
        sample_kernel<<<(warps + 7) / 8, 256>>>(Vh, OA, REF, ACCh);
    }
    // 7: Wo weight convert
    conv_w_kernel<<<(Dm * Dm + 255) / 256, 256>>>(Wo, Woh, Dm * Dm);
    // 8: A2h = ACC @ Wo + bo  (fp16 out)
    gemm_fp16_kernel<3><<<dim3(Dm / 128, rowBlocks), blk, SMEM_GEMM>>>(ACCh, Woh, bo, A2h, nullptr, NTOK, Dm, Dm);
    // 9: Xh = LN(Qh + A2h)
    add_layernorm_h_kernel<<<NTOK, 128>>>(Qh, A2h, g1, be1, Xh, nullptr);
    // 10: Hbh = fp16(relu(X @ W1 + b1))
    gemm_fp16_kernel<1><<<dim3(DFFm / 128, rowBlocks), blk, SMEM_GEMM>>>(Xh, W1h, b1, Hbh, nullptr, NTOK, Dm, DFFm);
    // 11: Yh = Hb @ W2 + b2  (fp16 out)
    gemm_fp16_kernel<3><<<dim3(Dm / 128, rowBlocks), blk, SMEM_GEMM>>>(Hbh, W2h, b2, Yh, nullptr, NTOK, DFFm, Dm);
    // 12: out = LN(Xh + Yh)  (fp32 to d_out)
    add_layernorm_h_kernel<<<NTOK, 128>>>(Xh, Yh, g2, be2, nullptr, out);
}